// round 1
// baseline (speedup 1.0000x reference)
#include <cuda_runtime.h>
#include <cuda_bf16.h>
#include <float.h>

// ---------------- problem constants ----------------
#define PB   8
#define PN   2048
#define PH   256
#define PL   4
#define PK   16
#define PG   512
#define PM0  256
#define PM1  128
#define PC   128
#define NPTS (PB * PN)           // 16384
#define EPS  1e-5f

// ---------------- device scratch (static, no allocation) ----------------
__device__ float g_h [NPTS * PH];          // residual stream        (16 MB)
__device__ float g_t [NPTS * PH];          // normalized features    (16 MB)
__device__ float g_u [NPTS * PH];          // x_i term / edge out    (16 MB)
__device__ float g_v [NPTS * PH];          // x_j term               (16 MB)
__device__ float g_sq[NPTS];
__device__ float g_d [(size_t)PB * PN * PN];   // distance matrix (134 MB)
__device__ int   g_idx[NPTS * PK];
__device__ float g_wd [PH * PH];           // We_A - We_B
__device__ float g_psum[64 * PH];
__device__ float g_psq [64 * PH];
__device__ float g_mean[PH];
__device__ float g_rstd[PH];
__device__ float g_big[(size_t)NPTS * PG]; // 32 MB
__device__ float g_pm [PB * 16 * PG];
__device__ float g_p  [PB * PG];

// ---------------- kernels ----------------

// h = x @ Wf + bf   (x: [p,3], Wf: [3,H])
__global__ void k_feat(const float* __restrict__ X, const float* __restrict__ Wf,
                       const float* __restrict__ bf, float* __restrict__ H) {
    int p = blockIdx.x, c = threadIdx.x;
    float x0 = X[p * 3 + 0], x1 = X[p * 3 + 1], x2 = X[p * 3 + 2];
    H[(size_t)p * PH + c] = x0 * Wf[c] + x1 * Wf[PH + c] + x2 * Wf[2 * PH + c] + bf[c];
}

// generic SGEMM: C[M,Nn] = A[M,Kc] @ W[Kc,Nn] (+ bias)
// MODE 0: store; MODE 1: C += alpha[li] * (acc + bias)   (residual update)
template<int MODE>
__global__ void __launch_bounds__(256)
k_gemm(const float* __restrict__ A, const float* __restrict__ W,
       const float* __restrict__ bias, float* __restrict__ C,
       int M, int Nn, int Kc, const float* __restrict__ alpha, int li) {
    __shared__ float As[16][65];
    __shared__ float Ws[16][64];
    int tid = threadIdx.x, tx = tid & 15, ty = tid >> 4;
    int n0 = blockIdx.x * 64, m0 = blockIdx.y * 64;
    float acc[4][4] = {};
    for (int k0 = 0; k0 < Kc; k0 += 16) {
#pragma unroll
        for (int e = 0; e < 4; e++) {
            int idx = tid + e * 256;
            int r = idx >> 4, c = idx & 15;
            As[c][r] = A[(size_t)(m0 + r) * Kc + k0 + c];
            int kk = idx >> 6, n = idx & 63;
            Ws[kk][n] = W[(size_t)(k0 + kk) * Nn + n0 + n];
        }
        __syncthreads();
#pragma unroll
        for (int kk = 0; kk < 16; kk++) {
            float a[4], w[4];
#pragma unroll
            for (int i = 0; i < 4; i++) a[i] = As[kk][ty * 4 + i];
#pragma unroll
            for (int j = 0; j < 4; j++) w[j] = Ws[kk][tx * 4 + j];
#pragma unroll
            for (int i = 0; i < 4; i++)
#pragma unroll
                for (int j = 0; j < 4; j++) acc[i][j] += a[i] * w[j];
        }
        __syncthreads();
    }
#pragma unroll
    for (int i = 0; i < 4; i++) {
        int row = m0 + ty * 4 + i;
#pragma unroll
        for (int j = 0; j < 4; j++) {
            int col = n0 + tx * 4 + j;
            float vv = acc[i][j] + (bias ? bias[col] : 0.0f);
            if (MODE == 0) C[(size_t)row * Nn + col] = vv;
            else           C[(size_t)row * Nn + col] += alpha[li] * vv;
        }
    }
}

// per-batch distance matrix: D[n,m] = sq[n] + sq[m] - 2 * <t_n, t_m>
__global__ void __launch_bounds__(256)
k_dist(const float* __restrict__ T, const float* __restrict__ SQ, float* __restrict__ D) {
    __shared__ float As[16][65];
    __shared__ float Bs[16][65];
    int b = blockIdx.z;
    const float* A = T + (size_t)b * PN * PH;
    float* Db = D + (size_t)b * PN * PN;
    const float* sqb = SQ + b * PN;
    int tid = threadIdx.x, tx = tid & 15, ty = tid >> 4;
    int n0 = blockIdx.y * 64, m0 = blockIdx.x * 64;
    float acc[4][4] = {};
    for (int k0 = 0; k0 < PH; k0 += 16) {
#pragma unroll
        for (int e = 0; e < 4; e++) {
            int idx = tid + e * 256;
            int r = idx >> 4, c = idx & 15;
            As[c][r] = A[(size_t)(n0 + r) * PH + k0 + c];
            Bs[c][r] = A[(size_t)(m0 + r) * PH + k0 + c];
        }
        __syncthreads();
#pragma unroll
        for (int kk = 0; kk < 16; kk++) {
            float a[4], w[4];
#pragma unroll
            for (int i = 0; i < 4; i++) a[i] = As[kk][ty * 4 + i];
#pragma unroll
            for (int j = 0; j < 4; j++) w[j] = Bs[kk][tx * 4 + j];
#pragma unroll
            for (int i = 0; i < 4; i++)
#pragma unroll
                for (int j = 0; j < 4; j++) acc[i][j] += a[i] * w[j];
        }
        __syncthreads();
    }
#pragma unroll
    for (int i = 0; i < 4; i++) {
        int n = n0 + ty * 4 + i;
        float sn = sqb[n];
#pragma unroll
        for (int j = 0; j < 4; j++) {
            int m = m0 + tx * 4 + j;
            Db[(size_t)n * PN + m] = sn + sqb[m] - 2.0f * acc[i][j];
        }
    }
}

// row sums of squares
__global__ void k_sq(const float* __restrict__ T, float* __restrict__ SQ) {
    int warp = threadIdx.x >> 5, lane = threadIdx.x & 31;
    int p = blockIdx.x * 8 + warp;
    const float* row = T + (size_t)p * PH;
    float s = 0.f;
    for (int k = lane; k < PH; k += 32) { float v = row[k]; s += v * v; }
#pragma unroll
    for (int o = 16; o > 0; o >>= 1) s += __shfl_down_sync(0xffffffffu, s, o);
    if (lane == 0) SQ[p] = s;
}

// 16 smallest distances per row (tie-break: lower index), matches lax.top_k(-d)
__global__ void k_topk(const float* __restrict__ D, int* __restrict__ IDX) {
    __shared__ float sd[PN];
    __shared__ float rv[256];
    __shared__ int   ri[256];
    int p = blockIdx.x, tid = threadIdx.x;
    const float* row = D + (size_t)p * PN;
    for (int i = tid; i < PN; i += 256) sd[i] = row[i];
    __syncthreads();
    for (int k = 0; k < PK; k++) {
        float bv = FLT_MAX; int bi = 0x7fffffff;
        for (int i = tid; i < PN; i += 256) {
            float v = sd[i];
            if (v < bv || (v == bv && i < bi)) { bv = v; bi = i; }
        }
        rv[tid] = bv; ri[tid] = bi;
        __syncthreads();
        for (int s = 128; s > 0; s >>= 1) {
            if (tid < s) {
                float v2 = rv[tid + s]; int i2 = ri[tid + s];
                if (v2 < rv[tid] || (v2 == rv[tid] && i2 < ri[tid])) { rv[tid] = v2; ri[tid] = i2; }
            }
            __syncthreads();
        }
        if (tid == 0) { IDX[p * PK + k] = ri[0]; sd[ri[0]] = FLT_MAX; }
        __syncthreads();
    }
}

// We diff: WD = We[0:H] - We[H:2H]
__global__ void k_wdiff(const float* __restrict__ We, float* __restrict__ WD) {
    int i = blockIdx.x * 256 + threadIdx.x;
    WD[i] = We[i] - We[PH * PH + i];
}

// OUT[p,h] = U[p,h] + max_k V[b, idx[p,k], h]   (in-place over U is safe)
__global__ void k_gathermax(const float* __restrict__ U, const float* __restrict__ V,
                            const int* __restrict__ IDX, float* __restrict__ OUT) {
    __shared__ int sidx[PK];
    int p = blockIdx.x, h = threadIdx.x;
    int b = p >> 11;
    if (h < PK) sidx[h] = IDX[p * PK + h];
    __syncthreads();
    float m = -FLT_MAX;
    int base = b * PN;
#pragma unroll
    for (int k = 0; k < PK; k++)
        m = fmaxf(m, V[(size_t)(base + sidx[k]) * PH + h]);
    OUT[(size_t)p * PH + h] = U[(size_t)p * PH + h] + m;
}

// batchnorm: deterministic two-stage stats
__global__ void k_bnpart(const float* __restrict__ X, float* __restrict__ psum, float* __restrict__ psq) {
    int blk = blockIdx.x, c = threadIdx.x;
    float s = 0.f, s2 = 0.f;
    int r0 = blk * 256;
    for (int r = 0; r < 256; r++) {
        float v = X[(size_t)(r0 + r) * PH + c];
        s += v; s2 += v * v;
    }
    psum[blk * PH + c] = s;
    psq [blk * PH + c] = s2;
}
__global__ void k_bnfin(const float* __restrict__ psum, const float* __restrict__ psq,
                        float* __restrict__ mean, float* __restrict__ rstd) {
    int c = threadIdx.x;
    float s = 0.f, s2 = 0.f;
    for (int b = 0; b < 64; b++) { s += psum[b * PH + c]; s2 += psq[b * PH + c]; }
    float m = s * (1.0f / NPTS);
    float var = s2 * (1.0f / NPTS) - m * m;
    mean[c] = m;
    rstd[c] = rsqrtf(var + EPS);
}
__global__ void k_bnapply(const float* __restrict__ X, float* __restrict__ Y,
                          const float* __restrict__ mean, const float* __restrict__ rstd,
                          const float* __restrict__ g, const float* __restrict__ bt) {
    int c = threadIdx.x;
    size_t i = (size_t)blockIdx.x * PH + c;
    float v = (X[i] - mean[c]) * rstd[c] * g[c] + bt[c];
    Y[i] = fmaxf(v, 0.0f);
}

// global max-pool over N, two stages
__global__ void k_pool1(const float* __restrict__ BIG, float* __restrict__ PM) {
    int b = blockIdx.x, chunk = blockIdx.y, g = threadIdx.x;
    float m = -FLT_MAX;
    int n0 = chunk * 128;
    for (int n = 0; n < 128; n++)
        m = fmaxf(m, BIG[(size_t)(b * PN + n0 + n) * PG + g]);
    PM[(b * 16 + chunk) * PG + g] = m;
}
__global__ void k_pool2(const float* __restrict__ PM, float* __restrict__ P) {
    int b = blockIdx.x, g = threadIdx.x;
    float m = -FLT_MAX;
    for (int c = 0; c < 16; c++) m = fmaxf(m, PM[(b * 16 + c) * PG + g]);
    P[b * PG + g] = m;
}

// tiny head MLP, one block per batch row
__global__ void k_mlp(const float* __restrict__ P,
                      const float* __restrict__ Wm1, const float* __restrict__ bm1,
                      const float* __restrict__ Wm2, const float* __restrict__ bm2,
                      const float* __restrict__ Wm3, const float* __restrict__ bm3,
                      float* __restrict__ OUT) {
    __shared__ float sp[PG], s1[PM0], s2[PM1];
    int b = blockIdx.x, tid = threadIdx.x;
    for (int j = tid; j < PG; j += 256) sp[j] = P[b * PG + j];
    __syncthreads();
    {
        float acc = bm1[tid];
        for (int k = 0; k < PG; k++) acc += sp[k] * Wm1[k * PM0 + tid];
        s1[tid] = fmaxf(acc, 0.0f);
    }
    __syncthreads();
    if (tid < PM1) {
        float acc = bm2[tid];
        for (int k = 0; k < PM0; k++) acc += s1[k] * Wm2[k * PM1 + tid];
        s2[tid] = fmaxf(acc, 0.0f);
    }
    __syncthreads();
    if (tid < PC) {
        float acc = bm3[tid];
        for (int k = 0; k < PM1; k++) acc += s2[k] * Wm3[k * PC + tid];
        OUT[b * PC + tid] = acc;
    }
}

// ---------------- host orchestration ----------------
extern "C" void kernel_launch(void* const* d_in, const int* in_sizes, int n_in,
                              void* d_out, int out_size) {
    const float* x    = (const float*)d_in[0];
    const float* Wf   = (const float*)d_in[2];
    const float* bf   = (const float*)d_in[3];
    const float* Wnn  = (const float*)d_in[4];
    const float* bnn  = (const float*)d_in[5];
    const float* g1   = (const float*)d_in[6];
    const float* b1   = (const float*)d_in[7];
    const float* We   = (const float*)d_in[8];
    const float* be   = (const float*)d_in[9];
    const float* g2   = (const float*)d_in[10];
    const float* b2   = (const float*)d_in[11];
    const float* Wl   = (const float*)d_in[12];
    const float* bl   = (const float*)d_in[13];
    const float* alpha= (const float*)d_in[14];
    const float* gg   = (const float*)d_in[15];
    const float* bgb  = (const float*)d_in[16];
    const float* Wg   = (const float*)d_in[17];
    const float* bg2  = (const float*)d_in[18];
    const float* Wm1  = (const float*)d_in[19];
    const float* bm1  = (const float*)d_in[20];
    const float* Wm2  = (const float*)d_in[21];
    const float* bm2  = (const float*)d_in[22];
    const float* Wm3  = (const float*)d_in[23];
    const float* bm3  = (const float*)d_in[24];

    float *h_, *t_, *u_, *v_, *sq_, *d_, *wd_, *psum_, *psq_, *mean_, *rstd_, *big_, *pm_, *p_;
    int* idx_;
    cudaGetSymbolAddress((void**)&h_,   g_h);
    cudaGetSymbolAddress((void**)&t_,   g_t);
    cudaGetSymbolAddress((void**)&u_,   g_u);
    cudaGetSymbolAddress((void**)&v_,   g_v);
    cudaGetSymbolAddress((void**)&sq_,  g_sq);
    cudaGetSymbolAddress((void**)&d_,   g_d);
    cudaGetSymbolAddress((void**)&idx_, g_idx);
    cudaGetSymbolAddress((void**)&wd_,  g_wd);
    cudaGetSymbolAddress((void**)&psum_,g_psum);
    cudaGetSymbolAddress((void**)&psq_, g_psq);
    cudaGetSymbolAddress((void**)&mean_,g_mean);
    cudaGetSymbolAddress((void**)&rstd_,g_rstd);
    cudaGetSymbolAddress((void**)&big_, g_big);
    cudaGetSymbolAddress((void**)&pm_,  g_pm);
    cudaGetSymbolAddress((void**)&p_,   g_p);

    // h = x @ Wf + bf
    k_feat<<<NPTS, PH>>>(x, Wf, bf, h_);

    for (int i = 0; i < PL; i++) {
        const float* src;
        if (i == 0) {
            k_gemm<0><<<dim3(PH / 64, NPTS / 64), 256>>>(h_, Wnn, bnn, t_, NPTS, PH, PH, nullptr, 0);
            src = t_;
        } else {
            src = h_;
        }
        // bn1 + relu -> t
        k_bnpart<<<64, 256>>>(src, psum_, psq_);
        k_bnfin<<<1, 256>>>(psum_, psq_, mean_, rstd_);
        k_bnapply<<<NPTS, 256>>>(src, t_, mean_, rstd_, g1 + i * PH, b1 + i * PH);
        // kNN graph on t
        k_sq<<<NPTS / 8, 256>>>(t_, sq_);
        k_dist<<<dim3(PN / 64, PN / 64, PB), 256>>>(t_, sq_, d_);
        k_topk<<<NPTS, 256>>>(d_, idx_);
        // edge conv (split form): u = t@(A-B)+be, v = t@B, out = u + max_k v[idx]
        k_wdiff<<<PH * PH / 256, 256>>>(We + (size_t)i * 2 * PH * PH, wd_);
        k_gemm<0><<<dim3(PH / 64, NPTS / 64), 256>>>(t_, wd_, be + i * PH, u_, NPTS, PH, PH, nullptr, 0);
        k_gemm<0><<<dim3(PH / 64, NPTS / 64), 256>>>(t_, We + (size_t)i * 2 * PH * PH + PH * PH, nullptr, v_, NPTS, PH, PH, nullptr, 0);
        k_gathermax<<<NPTS, 256>>>(u_, v_, idx_, u_);
        // bn2 + relu -> t
        k_bnpart<<<64, 256>>>(u_, psum_, psq_);
        k_bnfin<<<1, 256>>>(psum_, psq_, mean_, rstd_);
        k_bnapply<<<NPTS, 256>>>(u_, t_, mean_, rstd_, g2 + i * PH, b2 + i * PH);
        // h += alpha[i] * (t @ Wl + bl)
        k_gemm<1><<<dim3(PH / 64, NPTS / 64), 256>>>(t_, Wl + (size_t)i * PH * PH, bl + i * PH, h_, NPTS, PH, PH, alpha, i);
    }

    // head
    k_bnpart<<<64, 256>>>(h_, psum_, psq_);
    k_bnfin<<<1, 256>>>(psum_, psq_, mean_, rstd_);
    k_bnapply<<<NPTS, 256>>>(h_, t_, mean_, rstd_, gg, bgb);
    k_gemm<0><<<dim3(PG / 64, NPTS / 64), 256>>>(t_, Wg, bg2, big_, NPTS, PG, PH, nullptr, 0);
    k_pool1<<<dim3(PB, 16), PG>>>(big_, pm_);
    k_pool2<<<PB, PG>>>(pm_, p_);
    k_mlp<<<PB, 256>>>(p_, Wm1, bm1, Wm2, bm2, Wm3, bm3, (float*)d_out);
}

// round 2
// speedup vs baseline: 1.6953x; 1.6953x over previous
#include <cuda_runtime.h>
#include <cuda_bf16.h>
#include <float.h>

// ---------------- problem constants ----------------
#define PB   8
#define PN   2048
#define PH   256
#define PL   4
#define PK   16
#define PG   512
#define PM0  256
#define PM1  128
#define PC   128
#define NPTS (PB * PN)           // 16384
#define EPS  1e-5f

// ---------------- device scratch (static, no allocation) ----------------
__device__ float g_h [NPTS * PH];
__device__ float g_t [NPTS * PH];
__device__ float g_u [NPTS * PH];
__device__ float g_v [NPTS * PH];
__device__ float g_sq[NPTS];
__device__ float g_d [(size_t)PB * PN * PN];   // 134 MB
__device__ int   g_idx[NPTS * PK];
__device__ float g_wd [PH * PH];
__device__ float g_psum[128 * PH];
__device__ float g_psq [128 * PH];
__device__ float g_mean[PH];
__device__ float g_rstd[PH];
__device__ float g_big[(size_t)NPTS * PG];
__device__ float g_pm [PB * 16 * PG];
__device__ float g_p  [PB * PG];

// ---------------- small helpers ----------------
__device__ __forceinline__ unsigned long long pack2(float lo, float hi) {
    unsigned long long r;
    asm("mov.b64 %0, {%1, %2};" : "=l"(r) : "f"(lo), "f"(hi));
    return r;
}
__device__ __forceinline__ void unpack2(unsigned long long v, float& lo, float& hi) {
    asm("mov.b64 {%0, %1}, %2;" : "=f"(lo), "=f"(hi) : "l"(v));
}
__device__ __forceinline__ void fma2(unsigned long long& acc, unsigned long long a, unsigned long long b) {
    asm("fma.rn.f32x2 %0, %1, %2, %0;" : "+l"(acc) : "l"(a), "l"(b));
}

// ---------------- kernels ----------------

// h = x @ Wf + bf
__global__ void k_feat(const float* __restrict__ X, const float* __restrict__ Wf,
                       const float* __restrict__ bf, float* __restrict__ H) {
    int p = blockIdx.x, c = threadIdx.x;
    float x0 = X[p * 3 + 0], x1 = X[p * 3 + 1], x2 = X[p * 3 + 2];
    H[(size_t)p * PH + c] = x0 * Wf[c] + x1 * Wf[PH + c] + x2 * Wf[2 * PH + c] + bf[c];
}

// 128x128x8 SGEMM with packed f32x2 FMA.
// MODE 0: C = acc + bias (bias may be null); MODE 1: C += alpha[li]*(acc + bias)
template<int MODE>
__global__ void __launch_bounds__(256)
k_gemm128(const float* __restrict__ A, const float* __restrict__ W,
          const float* __restrict__ bias, float* __restrict__ C,
          int M, int Nn, int Kc, const float* __restrict__ alpha, int li) {
    __shared__ float As[8][128];
    __shared__ float Bs[8][128];
    int tid = threadIdx.x;
    int m0 = blockIdx.y * 128, n0 = blockIdx.x * 128;
    int ar = tid >> 1, ac = (tid & 1) * 4;           // A tile load coords
    int br = tid >> 5, bc = (tid & 31) * 4;          // B tile load coords
    int tx = tid & 15, ty = tid >> 4;                // output fragment coords

    unsigned long long acc2[8][4];
#pragma unroll
    for (int i = 0; i < 8; i++)
#pragma unroll
        for (int j = 0; j < 4; j++) acc2[i][j] = 0ull;

    const float* Aload = &A[(size_t)(m0 + ar) * Kc + ac];
    const float* Wload = &W[(size_t)br * Nn + n0 + bc];

    for (int k0 = 0; k0 < Kc; k0 += 8) {
        float4 av = *(const float4*)(Aload + k0);
        float4 bv = *(const float4*)(Wload + (size_t)k0 * Nn);
        __syncthreads();
        As[ac + 0][ar] = av.x; As[ac + 1][ar] = av.y;
        As[ac + 2][ar] = av.z; As[ac + 3][ar] = av.w;
        *(float4*)&Bs[br][bc] = bv;
        __syncthreads();
#pragma unroll
        for (int kk = 0; kk < 8; kk++) {
            float a_[8];
            *(float4*)&a_[0] = *(const float4*)&As[kk][ty * 8];
            *(float4*)&a_[4] = *(const float4*)&As[kk][ty * 8 + 4];
            ulonglong2 t0 = *(const ulonglong2*)&Bs[kk][tx * 8];
            ulonglong2 t1 = *(const ulonglong2*)&Bs[kk][tx * 8 + 4];
            unsigned long long b2[4] = {t0.x, t0.y, t1.x, t1.y};
#pragma unroll
            for (int i = 0; i < 8; i++) {
                unsigned long long a2 = pack2(a_[i], a_[i]);
#pragma unroll
                for (int j = 0; j < 4; j++) fma2(acc2[i][j], a2, b2[j]);
            }
        }
    }

    float al = (MODE == 1) ? alpha[li] : 0.0f;
#pragma unroll
    for (int i = 0; i < 8; i++) {
        int row = m0 + ty * 8 + i;
        float* crow = &C[(size_t)row * Nn + n0 + tx * 8];
#pragma unroll
        for (int half = 0; half < 2; half++) {
            float o0, o1, o2, o3;
            unpack2(acc2[i][half * 2 + 0], o0, o1);
            unpack2(acc2[i][half * 2 + 1], o2, o3);
            int col = n0 + tx * 8 + half * 4;
            if (bias) {
                o0 += bias[col + 0]; o1 += bias[col + 1];
                o2 += bias[col + 2]; o3 += bias[col + 3];
            }
            if (MODE == 0) {
                *(float4*)(crow + half * 4) = make_float4(o0, o1, o2, o3);
            } else {
                float4 c = *(float4*)(crow + half * 4);
                c.x += al * o0; c.y += al * o1; c.z += al * o2; c.w += al * o3;
                *(float4*)(crow + half * 4) = c;
            }
        }
    }
}

// distance matrix: D[n,m] = sq[n] + sq[m] - 2 * <t_n, t_m>, 128x128 tiles
__global__ void __launch_bounds__(256)
k_dist128(const float* __restrict__ T, const float* __restrict__ SQ, float* __restrict__ D) {
    __shared__ float As[8][128];
    __shared__ float Bs[8][128];
    int b = blockIdx.z;
    const float* A = T + (size_t)b * PN * PH;
    float* Db = D + (size_t)b * PN * PN;
    const float* sqb = SQ + b * PN;
    int tid = threadIdx.x;
    int n0 = blockIdx.y * 128, m0 = blockIdx.x * 128;
    int ar = tid >> 1, ac = (tid & 1) * 4;
    int tx = tid & 15, ty = tid >> 4;

    unsigned long long acc2[8][4];
#pragma unroll
    for (int i = 0; i < 8; i++)
#pragma unroll
        for (int j = 0; j < 4; j++) acc2[i][j] = 0ull;

    const float* Aload = &A[(size_t)(n0 + ar) * PH + ac];
    const float* Bload = &A[(size_t)(m0 + ar) * PH + ac];

    for (int k0 = 0; k0 < PH; k0 += 8) {
        float4 av = *(const float4*)(Aload + k0);
        float4 bv = *(const float4*)(Bload + k0);
        __syncthreads();
        As[ac + 0][ar] = av.x; As[ac + 1][ar] = av.y;
        As[ac + 2][ar] = av.z; As[ac + 3][ar] = av.w;
        Bs[ac + 0][ar] = bv.x; Bs[ac + 1][ar] = bv.y;
        Bs[ac + 2][ar] = bv.z; Bs[ac + 3][ar] = bv.w;
        __syncthreads();
#pragma unroll
        for (int kk = 0; kk < 8; kk++) {
            float a_[8];
            *(float4*)&a_[0] = *(const float4*)&As[kk][ty * 8];
            *(float4*)&a_[4] = *(const float4*)&As[kk][ty * 8 + 4];
            ulonglong2 t0 = *(const ulonglong2*)&Bs[kk][tx * 8];
            ulonglong2 t1 = *(const ulonglong2*)&Bs[kk][tx * 8 + 4];
            unsigned long long b2[4] = {t0.x, t0.y, t1.x, t1.y};
#pragma unroll
            for (int i = 0; i < 8; i++) {
                unsigned long long a2 = pack2(a_[i], a_[i]);
#pragma unroll
                for (int j = 0; j < 4; j++) fma2(acc2[i][j], a2, b2[j]);
            }
        }
    }

#pragma unroll
    for (int i = 0; i < 8; i++) {
        int n = n0 + ty * 8 + i;
        float sn = sqb[n];
        float* drow = &Db[(size_t)n * PN + m0 + tx * 8];
#pragma unroll
        for (int half = 0; half < 2; half++) {
            float o0, o1, o2, o3;
            unpack2(acc2[i][half * 2 + 0], o0, o1);
            unpack2(acc2[i][half * 2 + 1], o2, o3);
            int m = m0 + tx * 8 + half * 4;
            float4 out = make_float4(sn + sqb[m + 0] - 2.0f * o0,
                                     sn + sqb[m + 1] - 2.0f * o1,
                                     sn + sqb[m + 2] - 2.0f * o2,
                                     sn + sqb[m + 3] - 2.0f * o3);
            *(float4*)(drow + half * 4) = out;
        }
    }
}

// topk: one warp per row, 4 warps per block. Min-16 with lower-index tie-break.
__global__ void __launch_bounds__(128)
k_topk(const float* __restrict__ D, int* __restrict__ IDX) {
    __shared__ float sd[4][PN];
    int warp = threadIdx.x >> 5, lane = threadIdx.x & 31;
    int p = blockIdx.x * 4 + warp;
    const float* row = D + (size_t)p * PN;
    float* s = sd[warp];
    for (int i = lane; i < PN / 4; i += 32)
        ((float4*)s)[i] = ((const float4*)row)[i];
    __syncwarp();
    // lane owns strided elements: idx = lane + 32*j
    float bv = FLT_MAX; int bi = PN;
#pragma unroll 8
    for (int j = 0; j < PN / 32; j++) {
        int idx = lane + 32 * j;
        float v = s[idx];
        if (v < bv) { bv = v; bi = idx; }
    }
    for (int k = 0; k < PK; k++) {
        float v = bv; int i = bi;
#pragma unroll
        for (int o = 16; o > 0; o >>= 1) {
            float v2 = __shfl_xor_sync(0xffffffffu, v, o);
            int i2 = __shfl_xor_sync(0xffffffffu, i, o);
            if (v2 < v || (v2 == v && i2 < i)) { v = v2; i = i2; }
        }
        if (lane == 0) IDX[p * PK + k] = i;
        if ((i & 31) == lane) {
            s[i] = FLT_MAX;
            bv = FLT_MAX; bi = PN;
#pragma unroll 8
            for (int j = 0; j < PN / 32; j++) {
                int idx = lane + 32 * j;
                float w = s[idx];
                if (w < bv) { bv = w; bi = idx; }
            }
        }
        __syncwarp();
    }
}

__global__ void k_wdiff(const float* __restrict__ We, float* __restrict__ WD) {
    int i = blockIdx.x * 256 + threadIdx.x;
    WD[i] = We[i] - We[PH * PH + i];
}

// OUT[p,h] = U[p,h] + max_k V[b, idx[p,k], h]
__global__ void k_gathermax(const float* __restrict__ U, const float* __restrict__ V,
                            const int* __restrict__ IDX, float* __restrict__ OUT) {
    __shared__ int sidx[PK];
    int p = blockIdx.x, h = threadIdx.x;
    int b = p >> 11;
    if (h < PK) sidx[h] = IDX[p * PK + h];
    __syncthreads();
    float m = -FLT_MAX;
    int base = b * PN;
#pragma unroll
    for (int k = 0; k < PK; k++)
        m = fmaxf(m, V[(size_t)(base + sidx[k]) * PH + h]);
    OUT[(size_t)p * PH + h] = U[(size_t)p * PH + h] + m;
}

// batchnorm partials: 128 blocks x 128 rows
__global__ void k_bnpart(const float* __restrict__ X, float* __restrict__ psum, float* __restrict__ psq) {
    int blk = blockIdx.x, c = threadIdx.x;
    float s = 0.f, s2 = 0.f;
    int r0 = blk * 128;
    for (int r = 0; r < 128; r++) {
        float v = X[(size_t)(r0 + r) * PH + c];
        s += v; s2 += v * v;
    }
    psum[blk * PH + c] = s;
    psq [blk * PH + c] = s2;
}
__global__ void k_bnfin(const float* __restrict__ psum, const float* __restrict__ psq,
                        float* __restrict__ mean, float* __restrict__ rstd) {
    int c = threadIdx.x;
    float s = 0.f, s2 = 0.f;
#pragma unroll 16
    for (int b = 0; b < 128; b++) { s += psum[b * PH + c]; s2 += psq[b * PH + c]; }
    float m = s * (1.0f / NPTS);
    float var = s2 * (1.0f / NPTS) - m * m;
    mean[c] = m;
    rstd[c] = rsqrtf(var + EPS);
}
// bn apply + relu; optionally also emit row sum-of-squares (for kNN stage)
template<int WRITE_SQ>
__global__ void k_bnapply(const float* __restrict__ X, float* __restrict__ Y,
                          const float* __restrict__ mean, const float* __restrict__ rstd,
                          const float* __restrict__ g, const float* __restrict__ bt,
                          float* __restrict__ SQ) {
    __shared__ float red[8];
    int c = threadIdx.x;
    size_t i = (size_t)blockIdx.x * PH + c;
    float v = (X[i] - mean[c]) * rstd[c] * g[c] + bt[c];
    v = fmaxf(v, 0.0f);
    Y[i] = v;
    if (WRITE_SQ) {
        float s = v * v;
#pragma unroll
        for (int o = 16; o > 0; o >>= 1) s += __shfl_down_sync(0xffffffffu, s, o);
        if ((c & 31) == 0) red[c >> 5] = s;
        __syncthreads();
        if (c == 0) {
            float t = 0.f;
#pragma unroll
            for (int w = 0; w < 8; w++) t += red[w];
            SQ[blockIdx.x] = t;
        }
    }
}

// global max-pool over N, two stages
__global__ void k_pool1(const float* __restrict__ BIG, float* __restrict__ PM) {
    int b = blockIdx.x, chunk = blockIdx.y, g = threadIdx.x;
    float m = -FLT_MAX;
    int n0 = chunk * 128;
    for (int n = 0; n < 128; n++)
        m = fmaxf(m, BIG[(size_t)(b * PN + n0 + n) * PG + g]);
    PM[(b * 16 + chunk) * PG + g] = m;
}
__global__ void k_pool2(const float* __restrict__ PM, float* __restrict__ P) {
    int b = blockIdx.x, g = threadIdx.x;
    float m = -FLT_MAX;
    for (int c = 0; c < 16; c++) m = fmaxf(m, PM[(b * 16 + c) * PG + g]);
    P[b * PG + g] = m;
}

// head MLP
__global__ void k_mlp(const float* __restrict__ P,
                      const float* __restrict__ Wm1, const float* __restrict__ bm1,
                      const float* __restrict__ Wm2, const float* __restrict__ bm2,
                      const float* __restrict__ Wm3, const float* __restrict__ bm3,
                      float* __restrict__ OUT) {
    __shared__ float sp[PG], s1[PM0], s2[PM1];
    int b = blockIdx.x, tid = threadIdx.x;
    for (int j = tid; j < PG; j += 256) sp[j] = P[b * PG + j];
    __syncthreads();
    {
        float acc = bm1[tid];
        for (int k = 0; k < PG; k++) acc += sp[k] * Wm1[k * PM0 + tid];
        s1[tid] = fmaxf(acc, 0.0f);
    }
    __syncthreads();
    if (tid < PM1) {
        float acc = bm2[tid];
        for (int k = 0; k < PM0; k++) acc += s1[k] * Wm2[k * PM1 + tid];
        s2[tid] = fmaxf(acc, 0.0f);
    }
    __syncthreads();
    if (tid < PC) {
        float acc = bm3[tid];
        for (int k = 0; k < PM1; k++) acc += s2[k] * Wm3[k * PC + tid];
        OUT[b * PC + tid] = acc;
    }
}

// ---------------- host orchestration ----------------
extern "C" void kernel_launch(void* const* d_in, const int* in_sizes, int n_in,
                              void* d_out, int out_size) {
    const float* x    = (const float*)d_in[0];
    const float* Wf   = (const float*)d_in[2];
    const float* bf   = (const float*)d_in[3];
    const float* Wnn  = (const float*)d_in[4];
    const float* bnn  = (const float*)d_in[5];
    const float* g1   = (const float*)d_in[6];
    const float* b1   = (const float*)d_in[7];
    const float* We   = (const float*)d_in[8];
    const float* be   = (const float*)d_in[9];
    const float* g2   = (const float*)d_in[10];
    const float* b2   = (const float*)d_in[11];
    const float* Wl   = (const float*)d_in[12];
    const float* bl   = (const float*)d_in[13];
    const float* alpha= (const float*)d_in[14];
    const float* gg   = (const float*)d_in[15];
    const float* bgb  = (const float*)d_in[16];
    const float* Wg   = (const float*)d_in[17];
    const float* bg2  = (const float*)d_in[18];
    const float* Wm1  = (const float*)d_in[19];
    const float* bm1  = (const float*)d_in[20];
    const float* Wm2  = (const float*)d_in[21];
    const float* bm2  = (const float*)d_in[22];
    const float* Wm3  = (const float*)d_in[23];
    const float* bm3  = (const float*)d_in[24];

    float *h_, *t_, *u_, *v_, *sq_, *d_, *wd_, *psum_, *psq_, *mean_, *rstd_, *big_, *pm_, *p_;
    int* idx_;
    cudaGetSymbolAddress((void**)&h_,   g_h);
    cudaGetSymbolAddress((void**)&t_,   g_t);
    cudaGetSymbolAddress((void**)&u_,   g_u);
    cudaGetSymbolAddress((void**)&v_,   g_v);
    cudaGetSymbolAddress((void**)&sq_,  g_sq);
    cudaGetSymbolAddress((void**)&d_,   g_d);
    cudaGetSymbolAddress((void**)&idx_, g_idx);
    cudaGetSymbolAddress((void**)&wd_,  g_wd);
    cudaGetSymbolAddress((void**)&psum_,g_psum);
    cudaGetSymbolAddress((void**)&psq_, g_psq);
    cudaGetSymbolAddress((void**)&mean_,g_mean);
    cudaGetSymbolAddress((void**)&rstd_,g_rstd);
    cudaGetSymbolAddress((void**)&big_, g_big);
    cudaGetSymbolAddress((void**)&pm_,  g_pm);
    cudaGetSymbolAddress((void**)&p_,   g_p);

    k_feat<<<NPTS, PH>>>(x, Wf, bf, h_);

    for (int i = 0; i < PL; i++) {
        const float* src;
        if (i == 0) {
            k_gemm128<0><<<dim3(PH / 128, NPTS / 128), 256>>>(h_, Wnn, bnn, t_, NPTS, PH, PH, nullptr, 0);
            src = t_;
        } else {
            src = h_;
        }
        // bn1 + relu -> t (with fused row sumsq)
        k_bnpart<<<128, 256>>>(src, psum_, psq_);
        k_bnfin<<<1, 256>>>(psum_, psq_, mean_, rstd_);
        k_bnapply<1><<<NPTS, 256>>>(src, t_, mean_, rstd_, g1 + i * PH, b1 + i * PH, sq_);
        // kNN
        k_dist128<<<dim3(PN / 128, PN / 128, PB), 256>>>(t_, sq_, d_);
        k_topk<<<NPTS / 4, 128>>>(d_, idx_);
        // edge conv split form
        k_wdiff<<<PH * PH / 256, 256>>>(We + (size_t)i * 2 * PH * PH, wd_);
        k_gemm128<0><<<dim3(PH / 128, NPTS / 128), 256>>>(t_, wd_, be + i * PH, u_, NPTS, PH, PH, nullptr, 0);
        k_gemm128<0><<<dim3(PH / 128, NPTS / 128), 256>>>(t_, We + (size_t)i * 2 * PH * PH + PH * PH, nullptr, v_, NPTS, PH, PH, nullptr, 0);
        k_gathermax<<<NPTS, 256>>>(u_, v_, idx_, u_);
        // bn2 + relu -> t
        k_bnpart<<<128, 256>>>(u_, psum_, psq_);
        k_bnfin<<<1, 256>>>(psum_, psq_, mean_, rstd_);
        k_bnapply<0><<<NPTS, 256>>>(u_, t_, mean_, rstd_, g2 + i * PH, b2 + i * PH, nullptr);
        // h += alpha[i] * (t @ Wl + bl)
        k_gemm128<1><<<dim3(PH / 128, NPTS / 128), 256>>>(t_, Wl + (size_t)i * PH * PH, bl + i * PH, h_, NPTS, PH, PH, alpha, i);
    }

    // head
    k_bnpart<<<128, 256>>>(h_, psum_, psq_);
    k_bnfin<<<1, 256>>>(psum_, psq_, mean_, rstd_);
    k_bnapply<0><<<NPTS, 256>>>(h_, t_, mean_, rstd_, gg, bgb, nullptr);
    k_gemm128<0><<<dim3(PG / 128, NPTS / 128), 256>>>(t_, Wg, bg2, big_, NPTS, PG, PH, nullptr, 0);
    k_pool1<<<dim3(PB, 16), PG>>>(big_, pm_);
    k_pool2<<<PB, PG>>>(pm_, p_);
    k_mlp<<<PB, 256>>>(p_, Wm1, bm1, Wm2, bm2, Wm3, bm3, (float*)d_out);
}

// round 4
// speedup vs baseline: 2.1899x; 1.2917x over previous
#include <cuda_runtime.h>
#include <cuda_bf16.h>
#include <float.h>
#include <stdint.h>

// ---------------- problem constants ----------------
#define PB   8
#define PN   2048
#define PH   256
#define PL   4
#define PK   16
#define PG   512
#define PM0  256
#define PM1  128
#define PC   128
#define NPTS (PB * PN)           // 16384
#define EPS  1e-5f

// ---------------- device scratch ----------------
__device__ float g_h [NPTS * PH];
__device__ float g_t [NPTS * PH];
__device__ float g_u [NPTS * PH];
__device__ float g_v [NPTS * PH];
__device__ float g_sq[NPTS];
__device__ float g_d [(size_t)PB * PN * PN];   // 134 MB
__device__ int   g_idx[NPTS * PK];
__device__ float g_wd [PH * PH];
__device__ float g_psum[128 * PH];
__device__ float g_psq [128 * PH];
__device__ float g_mean[PH];
__device__ float g_rstd[PH];
__device__ float g_big[(size_t)NPTS * PG];
__device__ float g_pm [PB * 16 * PG];
__device__ float g_p  [PB * PG];
__device__ __nv_bfloat16 g_tp[(size_t)NPTS * 512];  // [hi(256) | lo(256)] per point

// ---------------- f32x2 helpers ----------------
__device__ __forceinline__ unsigned long long pack2(float lo, float hi) {
    unsigned long long r;
    asm("mov.b64 %0, {%1, %2};" : "=l"(r) : "f"(lo), "f"(hi));
    return r;
}
__device__ __forceinline__ void unpack2(unsigned long long v, float& lo, float& hi) {
    asm("mov.b64 {%0, %1}, %2;" : "=f"(lo), "=f"(hi) : "l"(v));
}
__device__ __forceinline__ void fma2(unsigned long long& acc, unsigned long long a, unsigned long long b) {
    asm("fma.rn.f32x2 %0, %1, %2, %0;" : "+l"(acc) : "l"(a), "l"(b));
}

// ---------------- mma.sync helpers ----------------
__device__ __forceinline__ uint32_t smem_u32(const void* p) {
    uint32_t a;
    asm("{ .reg .u64 t; cvta.to.shared.u64 t, %1; cvt.u32.u64 %0, t; }" : "=r"(a) : "l"(p));
    return a;
}
__device__ __forceinline__ void mma16816(float* c, const uint32_t* a, const uint32_t* b) {
    asm volatile("mma.sync.aligned.m16n8k16.row.col.f32.bf16.bf16.f32 "
        "{%0,%1,%2,%3}, {%4,%5,%6,%7}, {%8,%9}, {%0,%1,%2,%3};"
        : "+f"(c[0]), "+f"(c[1]), "+f"(c[2]), "+f"(c[3])
        : "r"(a[0]), "r"(a[1]), "r"(a[2]), "r"(a[3]), "r"(b[0]), "r"(b[1]));
}
// A fragment (16x16 bf16, row-major k-contig) via ldmatrix x4
__device__ __forceinline__ void ldmA(uint32_t* a, uint32_t base, int rbase, int ks, int lane) {
    int sub = lane >> 3;                         // 0..3
    int r = rbase + (sub & 1) * 8 + (lane & 7);
    int kb = ks * 32 + (sub >> 1) * 16;          // byte offset of k in row
    int chunk = (kb >> 4) ^ ((r >> 1) & 3);
    uint32_t addr = base + r * 64 + chunk * 16;
    asm volatile("ldmatrix.sync.aligned.m8n8.x4.shared.b16 {%0,%1,%2,%3}, [%4];"
        : "=r"(a[0]), "=r"(a[1]), "=r"(a[2]), "=r"(a[3]) : "r"(addr));
}
// B fragment (8 n-rows x 16 k, row-major k-contig) via ldmatrix x2 (non-trans)
__device__ __forceinline__ void ldmB(uint32_t* bfr, uint32_t base, int nbase, int ks, int lane) {
    int sub = (lane >> 3) & 1;
    int r = nbase + (lane & 7);
    int kb = ks * 32 + sub * 16;
    int chunk = (kb >> 4) ^ ((r >> 1) & 3);
    uint32_t addr = base + r * 64 + chunk * 16;
    asm volatile("ldmatrix.sync.aligned.m8n8.x2.shared.b16 {%0,%1}, [%2];"
        : "=r"(bfr[0]), "=r"(bfr[1]) : "r"(addr));
}

// ---------------- kernels ----------------

__global__ void k_feat(const float* __restrict__ X, const float* __restrict__ Wf,
                       const float* __restrict__ bf, float* __restrict__ H) {
    int p = blockIdx.x, c = threadIdx.x;
    float x0 = X[p * 3 + 0], x1 = X[p * 3 + 1], x2 = X[p * 3 + 2];
    H[(size_t)p * PH + c] = x0 * Wf[c] + x1 * Wf[PH + c] + x2 * Wf[2 * PH + c] + bf[c];
}

// 128x128x8 SGEMM with packed f32x2 FMA.
template<int MODE>
__global__ void __launch_bounds__(256)
k_gemm128(const float* __restrict__ A, const float* __restrict__ W,
          const float* __restrict__ bias, float* __restrict__ C,
          int M, int Nn, int Kc, const float* __restrict__ alpha, int li) {
    __shared__ float As[8][128];
    __shared__ float Bs[8][128];
    int tid = threadIdx.x;
    int m0 = blockIdx.y * 128, n0 = blockIdx.x * 128;
    int ar = tid >> 1, ac = (tid & 1) * 4;
    int br = tid >> 5, bc = (tid & 31) * 4;
    int tx = tid & 15, ty = tid >> 4;

    unsigned long long acc2[8][4];
#pragma unroll
    for (int i = 0; i < 8; i++)
#pragma unroll
        for (int j = 0; j < 4; j++) acc2[i][j] = 0ull;

    const float* Aload = &A[(size_t)(m0 + ar) * Kc + ac];
    const float* Wload = &W[(size_t)br * Nn + n0 + bc];

    for (int k0 = 0; k0 < Kc; k0 += 8) {
        float4 av = *(const float4*)(Aload + k0);
        float4 bv = *(const float4*)(Wload + (size_t)k0 * Nn);
        __syncthreads();
        As[ac + 0][ar] = av.x; As[ac + 1][ar] = av.y;
        As[ac + 2][ar] = av.z; As[ac + 3][ar] = av.w;
        *(float4*)&Bs[br][bc] = bv;
        __syncthreads();
#pragma unroll
        for (int kk = 0; kk < 8; kk++) {
            float a_[8];
            *(float4*)&a_[0] = *(const float4*)&As[kk][ty * 8];
            *(float4*)&a_[4] = *(const float4*)&As[kk][ty * 8 + 4];
            ulonglong2 t0 = *(const ulonglong2*)&Bs[kk][tx * 8];
            ulonglong2 t1 = *(const ulonglong2*)&Bs[kk][tx * 8 + 4];
            unsigned long long b2[4] = {t0.x, t0.y, t1.x, t1.y};
#pragma unroll
            for (int i = 0; i < 8; i++) {
                unsigned long long a2 = pack2(a_[i], a_[i]);
#pragma unroll
                for (int j = 0; j < 4; j++) fma2(acc2[i][j], a2, b2[j]);
            }
        }
    }

    float al = (MODE == 1) ? alpha[li] : 0.0f;
#pragma unroll
    for (int i = 0; i < 8; i++) {
        int row = m0 + ty * 8 + i;
        float* crow = &C[(size_t)row * Nn + n0 + tx * 8];
#pragma unroll
        for (int half = 0; half < 2; half++) {
            float o0, o1, o2, o3;
            unpack2(acc2[i][half * 2 + 0], o0, o1);
            unpack2(acc2[i][half * 2 + 1], o2, o3);
            int col = n0 + tx * 8 + half * 4;
            if (bias) {
                o0 += bias[col + 0]; o1 += bias[col + 1];
                o2 += bias[col + 2]; o3 += bias[col + 3];
            }
            if (MODE == 0) {
                *(float4*)(crow + half * 4) = make_float4(o0, o1, o2, o3);
            } else {
                float4 c = *(float4*)(crow + half * 4);
                c.x += al * o0; c.y += al * o1; c.z += al * o2; c.w += al * o3;
                *(float4*)(crow + half * 4) = c;
            }
        }
    }
}

// split t into bf16 hi/lo planes: TP[p][0..255]=hi, TP[p][256..511]=lo
__global__ void k_split(const float* __restrict__ T, __nv_bfloat16* __restrict__ TP) {
    int p = blockIdx.x, f = threadIdx.x;
    float v = T[(size_t)p * PH + f];
    __nv_bfloat16 hi = __float2bfloat16(v);
    float rem = v - __bfloat162float(hi);
    __nv_bfloat16 lo = __float2bfloat16(rem);
    TP[(size_t)p * 512 + f] = hi;
    TP[(size_t)p * 512 + 256 + f] = lo;
}

// HMMA distance kernel: 128(n) x 128(m) per CTA, split-bf16 compensated (K=768).
// chunks 0-7: hi*hi, 8-15: hi*lo, 16-23: lo*hi
__global__ void __launch_bounds__(256)
k_dist_mma(const __nv_bfloat16* __restrict__ TP, const float* __restrict__ SQ,
           float* __restrict__ D) {
    __shared__ __nv_bfloat16 As[2][128 * 32];
    __shared__ __nv_bfloat16 Bs[2][128 * 32];
    int b = blockIdx.z;
    int n0 = blockIdx.y * 128, m0 = blockIdx.x * 128;
    const __nv_bfloat16* tp = TP + (size_t)b * PN * 512;
    const float* sqb = SQ + b * PN;
    float* Db = D + (size_t)b * PN * PN;
    int tid = threadIdx.x, lane = tid & 31, warp = tid >> 5;
    int wr = warp & 3, wc = warp >> 2;   // warp tile: rows n0+32*wr, cols m0+64*wc

    uint32_t baseA[2] = { smem_u32(As[0]), smem_u32(As[1]) };
    uint32_t baseB[2] = { smem_u32(Bs[0]), smem_u32(Bs[1]) };

    float acc[2][8][4];
#pragma unroll
    for (int i = 0; i < 2; i++)
#pragma unroll
        for (int j = 0; j < 8; j++)
#pragma unroll
            for (int q = 0; q < 4; q++) acc[i][j][q] = 0.0f;

    int i0 = tid, i1 = tid + 256;
    int rA0 = i0 >> 2, cA0 = i0 & 3, rA1 = i1 >> 2, cA1 = i1 & 3;
    uint32_t sA0 = (uint32_t)rA0 * 64 + (uint32_t)((cA0 ^ ((rA0 >> 1) & 3)) * 16);
    uint32_t sA1 = (uint32_t)rA1 * 64 + (uint32_t)((cA1 ^ ((rA1 >> 1) & 3)) * 16);

    auto featA = [](int ch) { return ((ch >> 3) == 2 ? 256 : 0) + (ch & 7) * 32; };
    auto featB = [](int ch) { return ((ch >> 3) == 1 ? 256 : 0) + (ch & 7) * 32; };

    // preload chunk 0 into stage 0
    {
        int fa = featA(0), fb = featB(0);
        uint4 a0 = *(const uint4*)&tp[(size_t)(n0 + rA0) * 512 + fa + cA0 * 8];
        uint4 a1 = *(const uint4*)&tp[(size_t)(n0 + rA1) * 512 + fa + cA1 * 8];
        uint4 b0 = *(const uint4*)&tp[(size_t)(m0 + rA0) * 512 + fb + cA0 * 8];
        uint4 b1 = *(const uint4*)&tp[(size_t)(m0 + rA1) * 512 + fb + cA1 * 8];
        *(uint4*)((char*)As[0] + sA0) = a0;
        *(uint4*)((char*)As[0] + sA1) = a1;
        *(uint4*)((char*)Bs[0] + sA0) = b0;
        *(uint4*)((char*)Bs[0] + sA1) = b1;
    }
    __syncthreads();

    for (int ch = 0; ch < 24; ch++) {
        int s = ch & 1;
        uint4 pa0, pa1, pb0, pb1;
        if (ch + 1 < 24) {
            int fa = featA(ch + 1), fb = featB(ch + 1);
            pa0 = *(const uint4*)&tp[(size_t)(n0 + rA0) * 512 + fa + cA0 * 8];
            pa1 = *(const uint4*)&tp[(size_t)(n0 + rA1) * 512 + fa + cA1 * 8];
            pb0 = *(const uint4*)&tp[(size_t)(m0 + rA0) * 512 + fb + cA0 * 8];
            pb1 = *(const uint4*)&tp[(size_t)(m0 + rA1) * 512 + fb + cA1 * 8];
        }
#pragma unroll
        for (int ks = 0; ks < 2; ks++) {
            uint32_t afr0[4], afr1[4];
            ldmA(afr0, baseA[s], wr * 32, ks, lane);
            ldmA(afr1, baseA[s], wr * 32 + 16, ks, lane);
#pragma unroll
            for (int nt = 0; nt < 8; nt++) {
                uint32_t bfr[2];
                ldmB(bfr, baseB[s], wc * 64 + nt * 8, ks, lane);
                mma16816(acc[0][nt], afr0, bfr);
                mma16816(acc[1][nt], afr1, bfr);
            }
        }
        if (ch + 1 < 24) {
            int s2 = s ^ 1;
            *(uint4*)((char*)As[s2] + sA0) = pa0;
            *(uint4*)((char*)As[s2] + sA1) = pa1;
            *(uint4*)((char*)Bs[s2] + sA0) = pb0;
            *(uint4*)((char*)Bs[s2] + sA1) = pb1;
        }
        __syncthreads();
    }

    // epilogue: D[n][m] = sq[n] + sq[m] - 2*acc
#pragma unroll
    for (int mt = 0; mt < 2; mt++) {
        int r = n0 + wr * 32 + mt * 16 + (lane >> 2);
        float sn0 = sqb[r], sn1 = sqb[r + 8];
#pragma unroll
        for (int nt = 0; nt < 8; nt++) {
            int c = m0 + wc * 64 + nt * 8 + (lane & 3) * 2;
            float sm0 = sqb[c], sm1 = sqb[c + 1];
            float* a = acc[mt][nt];
            *(float2*)&Db[(size_t)r * PN + c] =
                make_float2(sn0 + sm0 - 2.0f * a[0], sn0 + sm1 - 2.0f * a[1]);
            *(float2*)&Db[(size_t)(r + 8) * PN + c] =
                make_float2(sn1 + sm0 - 2.0f * a[2], sn1 + sm1 - 2.0f * a[3]);
        }
    }
}

// topk: one warp per row
__global__ void __launch_bounds__(128)
k_topk(const float* __restrict__ D, int* __restrict__ IDX) {
    __shared__ float sd[4][PN];
    int warp = threadIdx.x >> 5, lane = threadIdx.x & 31;
    int p = blockIdx.x * 4 + warp;
    const float* row = D + (size_t)p * PN;
    float* s = sd[warp];
    for (int i = lane; i < PN / 4; i += 32)
        ((float4*)s)[i] = ((const float4*)row)[i];
    __syncwarp();
    float bv = FLT_MAX; int bi = PN;
#pragma unroll 8
    for (int j = 0; j < PN / 32; j++) {
        int idx = lane + 32 * j;
        float v = s[idx];
        if (v < bv) { bv = v; bi = idx; }
    }
    for (int k = 0; k < PK; k++) {
        float v = bv; int i = bi;
#pragma unroll
        for (int o = 16; o > 0; o >>= 1) {
            float v2 = __shfl_xor_sync(0xffffffffu, v, o);
            int i2 = __shfl_xor_sync(0xffffffffu, i, o);
            if (v2 < v || (v2 == v && i2 < i)) { v = v2; i = i2; }
        }
        if (lane == 0) IDX[p * PK + k] = i;
        if ((i & 31) == lane) {
            s[i] = FLT_MAX;
            bv = FLT_MAX; bi = PN;
#pragma unroll 8
            for (int j = 0; j < PN / 32; j++) {
                int idx = lane + 32 * j;
                float w = s[idx];
                if (w < bv) { bv = w; bi = idx; }
            }
        }
        __syncwarp();
    }
}

__global__ void k_wdiff(const float* __restrict__ We, float* __restrict__ WD) {
    int i = blockIdx.x * 256 + threadIdx.x;
    WD[i] = We[i] - We[PH * PH + i];
}

__global__ void k_gathermax(const float* __restrict__ U, const float* __restrict__ V,
                            const int* __restrict__ IDX, float* __restrict__ OUT) {
    __shared__ int sidx[PK];
    int p = blockIdx.x, h = threadIdx.x;
    int b = p >> 11;
    if (h < PK) sidx[h] = IDX[p * PK + h];
    __syncthreads();
    float m = -FLT_MAX;
    int base = b * PN;
#pragma unroll
    for (int k = 0; k < PK; k++)
        m = fmaxf(m, V[(size_t)(base + sidx[k]) * PH + h]);
    OUT[(size_t)p * PH + h] = U[(size_t)p * PH + h] + m;
}

__global__ void k_bnpart(const float* __restrict__ X, float* __restrict__ psum, float* __restrict__ psq) {
    int blk = blockIdx.x, c = threadIdx.x;
    float s = 0.f, s2 = 0.f;
    int r0 = blk * 128;
    for (int r = 0; r < 128; r++) {
        float v = X[(size_t)(r0 + r) * PH + c];
        s += v; s2 += v * v;
    }
    psum[blk * PH + c] = s;
    psq [blk * PH + c] = s2;
}
__global__ void k_bnfin(const float* __restrict__ psum, const float* __restrict__ psq,
                        float* __restrict__ mean, float* __restrict__ rstd) {
    int c = threadIdx.x;
    float s = 0.f, s2 = 0.f;
#pragma unroll 16
    for (int b = 0; b < 128; b++) { s += psum[b * PH + c]; s2 += psq[b * PH + c]; }
    float m = s * (1.0f / NPTS);
    float var = s2 * (1.0f / NPTS) - m * m;
    mean[c] = m;
    rstd[c] = rsqrtf(var + EPS);
}
template<int WRITE_SQ>
__global__ void k_bnapply(const float* __restrict__ X, float* __restrict__ Y,
                          const float* __restrict__ mean, const float* __restrict__ rstd,
                          const float* __restrict__ g, const float* __restrict__ bt,
                          float* __restrict__ SQ) {
    __shared__ float red[8];
    int c = threadIdx.x;
    size_t i = (size_t)blockIdx.x * PH + c;
    float v = (X[i] - mean[c]) * rstd[c] * g[c] + bt[c];
    v = fmaxf(v, 0.0f);
    Y[i] = v;
    if (WRITE_SQ) {
        float s = v * v;
#pragma unroll
        for (int o = 16; o > 0; o >>= 1) s += __shfl_down_sync(0xffffffffu, s, o);
        if ((c & 31) == 0) red[c >> 5] = s;
        __syncthreads();
        if (c == 0) {
            float t = 0.f;
#pragma unroll
            for (int w = 0; w < 8; w++) t += red[w];
            SQ[blockIdx.x] = t;
        }
    }
}

__global__ void k_pool1(const float* __restrict__ BIG, float* __restrict__ PM) {
    int b = blockIdx.x, chunk = blockIdx.y, g = threadIdx.x;
    float m = -FLT_MAX;
    int n0 = chunk * 128;
    for (int n = 0; n < 128; n++)
        m = fmaxf(m, BIG[(size_t)(b * PN + n0 + n) * PG + g]);
    PM[(b * 16 + chunk) * PG + g] = m;
}
__global__ void k_pool2(const float* __restrict__ PM, float* __restrict__ P) {
    int b = blockIdx.x, g = threadIdx.x;
    float m = -FLT_MAX;
    for (int c = 0; c < 16; c++) m = fmaxf(m, PM[(b * 16 + c) * PG + g]);
    P[b * PG + g] = m;
}

__global__ void k_mlp(const float* __restrict__ P,
                      const float* __restrict__ Wm1, const float* __restrict__ bm1,
                      const float* __restrict__ Wm2, const float* __restrict__ bm2,
                      const float* __restrict__ Wm3, const float* __restrict__ bm3,
                      float* __restrict__ OUT) {
    __shared__ float sp[PG], s1[PM0], s2[PM1];
    int b = blockIdx.x, tid = threadIdx.x;
    for (int j = tid; j < PG; j += 256) sp[j] = P[b * PG + j];
    __syncthreads();
    {
        float acc = bm1[tid];
        for (int k = 0; k < PG; k++) acc += sp[k] * Wm1[k * PM0 + tid];
        s1[tid] = fmaxf(acc, 0.0f);
    }
    __syncthreads();
    if (tid < PM1) {
        float acc = bm2[tid];
        for (int k = 0; k < PM0; k++) acc += s1[k] * Wm2[k * PM1 + tid];
        s2[tid] = fmaxf(acc, 0.0f);
    }
    __syncthreads();
    if (tid < PC) {
        float acc = bm3[tid];
        for (int k = 0; k < PM1; k++) acc += s2[k] * Wm3[k * PC + tid];
        OUT[b * PC + tid] = acc;
    }
}

// ---------------- host orchestration ----------------
extern "C" void kernel_launch(void* const* d_in, const int* in_sizes, int n_in,
                              void* d_out, int out_size) {
    const float* x    = (const float*)d_in[0];
    const float* Wf   = (const float*)d_in[2];
    const float* bf   = (const float*)d_in[3];
    const float* Wnn  = (const float*)d_in[4];
    const float* bnn  = (const float*)d_in[5];
    const float* g1   = (const float*)d_in[6];
    const float* b1   = (const float*)d_in[7];
    const float* We   = (const float*)d_in[8];
    const float* be   = (const float*)d_in[9];
    const float* g2   = (const float*)d_in[10];
    const float* b2   = (const float*)d_in[11];
    const float* Wl   = (const float*)d_in[12];
    const float* bl   = (const float*)d_in[13];
    const float* alpha= (const float*)d_in[14];
    const float* gg   = (const float*)d_in[15];
    const float* bgb  = (const float*)d_in[16];
    const float* Wg   = (const float*)d_in[17];
    const float* bg2  = (const float*)d_in[18];
    const float* Wm1  = (const float*)d_in[19];
    const float* bm1  = (const float*)d_in[20];
    const float* Wm2  = (const float*)d_in[21];
    const float* bm2  = (const float*)d_in[22];
    const float* Wm3  = (const float*)d_in[23];
    const float* bm3  = (const float*)d_in[24];

    float *h_, *t_, *u_, *v_, *sq_, *d_, *wd_, *psum_, *psq_, *mean_, *rstd_, *big_, *pm_, *p_;
    int* idx_;
    __nv_bfloat16* tp_;
    cudaGetSymbolAddress((void**)&h_,   g_h);
    cudaGetSymbolAddress((void**)&t_,   g_t);
    cudaGetSymbolAddress((void**)&u_,   g_u);
    cudaGetSymbolAddress((void**)&v_,   g_v);
    cudaGetSymbolAddress((void**)&sq_,  g_sq);
    cudaGetSymbolAddress((void**)&d_,   g_d);
    cudaGetSymbolAddress((void**)&idx_, g_idx);
    cudaGetSymbolAddress((void**)&wd_,  g_wd);
    cudaGetSymbolAddress((void**)&psum_,g_psum);
    cudaGetSymbolAddress((void**)&psq_, g_psq);
    cudaGetSymbolAddress((void**)&mean_,g_mean);
    cudaGetSymbolAddress((void**)&rstd_,g_rstd);
    cudaGetSymbolAddress((void**)&big_, g_big);
    cudaGetSymbolAddress((void**)&pm_,  g_pm);
    cudaGetSymbolAddress((void**)&p_,   g_p);
    cudaGetSymbolAddress((void**)&tp_,  g_tp);

    k_feat<<<NPTS, PH>>>(x, Wf, bf, h_);

    for (int i = 0; i < PL; i++) {
        const float* src;
        if (i == 0) {
            k_gemm128<0><<<dim3(PH / 128, NPTS / 128), 256>>>(h_, Wnn, bnn, t_, NPTS, PH, PH, nullptr, 0);
            src = t_;
        } else {
            src = h_;
        }
        k_bnpart<<<128, 256>>>(src, psum_, psq_);
        k_bnfin<<<1, 256>>>(psum_, psq_, mean_, rstd_);
        k_bnapply<1><<<NPTS, 256>>>(src, t_, mean_, rstd_, g1 + i * PH, b1 + i * PH, sq_);
        // kNN via HMMA (split bf16)
        k_split<<<NPTS, 256>>>(t_, tp_);
        k_dist_mma<<<dim3(PN / 128, PN / 128, PB), 256>>>(tp_, sq_, d_);
        k_topk<<<NPTS / 4, 128>>>(d_, idx_);
        // edge conv split form
        k_wdiff<<<PH * PH / 256, 256>>>(We + (size_t)i * 2 * PH * PH, wd_);
        k_gemm128<0><<<dim3(PH / 128, NPTS / 128), 256>>>(t_, wd_, be + i * PH, u_, NPTS, PH, PH, nullptr, 0);
        k_gemm128<0><<<dim3(PH / 128, NPTS / 128), 256>>>(t_, We + (size_t)i * 2 * PH * PH + PH * PH, nullptr, v_, NPTS, PH, PH, nullptr, 0);
        k_gathermax<<<NPTS, 256>>>(u_, v_, idx_, u_);
        k_bnpart<<<128, 256>>>(u_, psum_, psq_);
        k_bnfin<<<1, 256>>>(psum_, psq_, mean_, rstd_);
        k_bnapply<0><<<NPTS, 256>>>(u_, t_, mean_, rstd_, g2 + i * PH, b2 + i * PH, nullptr);
        k_gemm128<1><<<dim3(PH / 128, NPTS / 128), 256>>>(t_, Wl + (size_t)i * PH * PH, bl + i * PH, h_, NPTS, PH, PH, alpha, i);
    }

    k_bnpart<<<128, 256>>>(h_, psum_, psq_);
    k_bnfin<<<1, 256>>>(psum_, psq_, mean_, rstd_);
    k_bnapply<0><<<NPTS, 256>>>(h_, t_, mean_, rstd_, gg, bgb, nullptr);
    k_gemm128<0><<<dim3(PG / 128, NPTS / 128), 256>>>(t_, Wg, bg2, big_, NPTS, PG, PH, nullptr, 0);
    k_pool1<<<dim3(PB, 16), PG>>>(big_, pm_);
    k_pool2<<<PB, PG>>>(pm_, p_);
    k_mlp<<<PB, 256>>>(p_, Wm1, bm1, Wm2, bm2, Wm3, bm3, (float*)d_out);
}

// round 5
// speedup vs baseline: 2.5721x; 1.1746x over previous
#include <cuda_runtime.h>
#include <cuda_bf16.h>
#include <float.h>
#include <stdint.h>

// ---------------- problem constants ----------------
#define PB   8
#define PN   2048
#define PH   256
#define PL   4
#define PK   16
#define PG   512
#define PM0  256
#define PM1  128
#define PC   128
#define NPTS (PB * PN)           // 16384
#define EPS  1e-5f

// ---------------- device scratch ----------------
__device__ float g_h [NPTS * PH];
__device__ float g_t [NPTS * PH];
__device__ float g_u [NPTS * PH];
__device__ float g_v [NPTS * PH];
__device__ float g_sq[NPTS];
__device__ float g_d [(size_t)PB * PN * PN];   // 134 MB
__device__ int   g_idx[NPTS * PK];
__device__ float g_psum[128 * PH];
__device__ float g_psq [128 * PH];
__device__ float g_mean[PH];
__device__ float g_rstd[PH];
__device__ float g_big[(size_t)NPTS * PG];
__device__ float g_pm [PB * 16 * PG];
__device__ float g_p  [PB * PG];
__device__ __nv_bfloat16 g_tp [(size_t)NPTS * 512];  // activations: [hi(256) | lo(256)] per row
__device__ __nv_bfloat16 g_wt1[512 * 512];           // weight T split: [hi(256) | lo(256)] per out-col
__device__ __nv_bfloat16 g_wt2[512 * 512];

// ---------------- mma.sync helpers ----------------
__device__ __forceinline__ uint32_t smem_u32(const void* p) {
    uint32_t a;
    asm("{ .reg .u64 t; cvta.to.shared.u64 t, %1; cvt.u32.u64 %0, t; }" : "=r"(a) : "l"(p));
    return a;
}
__device__ __forceinline__ void mma16816(float* c, const uint32_t* a, const uint32_t* b) {
    asm volatile("mma.sync.aligned.m16n8k16.row.col.f32.bf16.bf16.f32 "
        "{%0,%1,%2,%3}, {%4,%5,%6,%7}, {%8,%9}, {%0,%1,%2,%3};"
        : "+f"(c[0]), "+f"(c[1]), "+f"(c[2]), "+f"(c[3])
        : "r"(a[0]), "r"(a[1]), "r"(a[2]), "r"(a[3]), "r"(b[0]), "r"(b[1]));
}
__device__ __forceinline__ void ldmA(uint32_t* a, uint32_t base, int rbase, int ks, int lane) {
    int sub = lane >> 3;
    int r = rbase + (sub & 1) * 8 + (lane & 7);
    int kb = ks * 32 + (sub >> 1) * 16;
    int chunk = (kb >> 4) ^ ((r >> 1) & 3);
    uint32_t addr = base + r * 64 + chunk * 16;
    asm volatile("ldmatrix.sync.aligned.m8n8.x4.shared.b16 {%0,%1,%2,%3}, [%4];"
        : "=r"(a[0]), "=r"(a[1]), "=r"(a[2]), "=r"(a[3]) : "r"(addr));
}
__device__ __forceinline__ void ldmB(uint32_t* bfr, uint32_t base, int nbase, int ks, int lane) {
    int sub = (lane >> 3) & 1;
    int r = nbase + (lane & 7);
    int kb = ks * 32 + sub * 16;
    int chunk = (kb >> 4) ^ ((r >> 1) & 3);
    uint32_t addr = base + r * 64 + chunk * 16;
    asm volatile("ldmatrix.sync.aligned.m8n8.x2.shared.b16 {%0,%1}, [%2];"
        : "=r"(bfr[0]), "=r"(bfr[1]) : "r"(addr));
}
// term schedule: groups of 8 chunks: 0-7 hiA*hiB, 8-15 hiA*loB, 16-23 loA*hiB
__device__ __forceinline__ int featA(int ch) { return ((ch >> 3) == 2 ? 256 : 0) + (ch & 7) * 32; }
__device__ __forceinline__ int featB(int ch) { return ((ch >> 3) == 1 ? 256 : 0) + (ch & 7) * 32; }

// ---------------- kernels ----------------

__global__ void k_feat(const float* __restrict__ X, const float* __restrict__ Wf,
                       const float* __restrict__ bf, float* __restrict__ H) {
    int p = blockIdx.x, c = threadIdx.x;
    float x0 = X[p * 3 + 0], x1 = X[p * 3 + 1], x2 = X[p * 3 + 2];
    H[(size_t)p * PH + c] = x0 * Wf[c] + x1 * Wf[PH + c] + x2 * Wf[2 * PH + c] + bf[c];
}

// split activations into bf16 hi/lo planes: TP[p][0..255]=hi, TP[p][256..511]=lo
__global__ void k_split(const float* __restrict__ T, __nv_bfloat16* __restrict__ TP) {
    int p = blockIdx.x, f = threadIdx.x;
    float v = T[(size_t)p * PH + f];
    __nv_bfloat16 hi = __float2bfloat16(v);
    float rem = v - __bfloat162float(hi);
    TP[(size_t)p * 512 + f] = hi;
    TP[(size_t)p * 512 + 256 + f] = __float2bfloat16(rem);
}

// weight transpose + split (optionally W - Wsub): WT[n][k]=hi, WT[n][256+k]=lo
__global__ void k_wtsplit(const float* __restrict__ W, const float* __restrict__ Wsub,
                          __nv_bfloat16* __restrict__ WT, int Nn) {
    int n = blockIdx.x, k = threadIdx.x;
    float v = W[(size_t)k * Nn + n];
    if (Wsub) v -= Wsub[(size_t)k * Nn + n];
    __nv_bfloat16 hi = __float2bfloat16(v);
    float rem = v - __bfloat162float(hi);
    WT[(size_t)n * 512 + k] = hi;
    WT[(size_t)n * 512 + 256 + k] = __float2bfloat16(rem);
}

// Generic split-bf16 HMMA GEMM: C[M,Nn] = A@W (+bias), K=256 (24 chunk iters).
// MODE 0: C = acc + bias;  MODE 1: C += alpha[li]*(acc + bias)
template<int MODE>
__global__ void __launch_bounds__(256)
k_gemm_mma(const __nv_bfloat16* __restrict__ TP, const __nv_bfloat16* __restrict__ WT,
           const float* __restrict__ bias, float* __restrict__ C, int Nn,
           const float* __restrict__ alpha, int li) {
    __shared__ __nv_bfloat16 As[2][128 * 32];
    __shared__ __nv_bfloat16 Bs[2][128 * 32];
    int n0 = blockIdx.x * 128, m0 = blockIdx.y * 128;
    int tid = threadIdx.x, lane = tid & 31, warp = tid >> 5;
    int wr = warp & 3, wc = warp >> 2;

    uint32_t baseA[2] = { smem_u32(As[0]), smem_u32(As[1]) };
    uint32_t baseB[2] = { smem_u32(Bs[0]), smem_u32(Bs[1]) };

    float acc[2][8][4];
#pragma unroll
    for (int i = 0; i < 2; i++)
#pragma unroll
        for (int j = 0; j < 8; j++)
#pragma unroll
            for (int q = 0; q < 4; q++) acc[i][j][q] = 0.0f;

    int i0 = tid, i1 = tid + 256;
    int rA0 = i0 >> 2, cA0 = i0 & 3, rA1 = i1 >> 2, cA1 = i1 & 3;
    uint32_t sA0 = (uint32_t)rA0 * 64 + (uint32_t)((cA0 ^ ((rA0 >> 1) & 3)) * 16);
    uint32_t sA1 = (uint32_t)rA1 * 64 + (uint32_t)((cA1 ^ ((rA1 >> 1) & 3)) * 16);

    {
        int fa = featA(0), fb = featB(0);
        *(uint4*)((char*)As[0] + sA0) = *(const uint4*)&TP[(size_t)(m0 + rA0) * 512 + fa + cA0 * 8];
        *(uint4*)((char*)As[0] + sA1) = *(const uint4*)&TP[(size_t)(m0 + rA1) * 512 + fa + cA1 * 8];
        *(uint4*)((char*)Bs[0] + sA0) = *(const uint4*)&WT[(size_t)(n0 + rA0) * 512 + fb + cA0 * 8];
        *(uint4*)((char*)Bs[0] + sA1) = *(const uint4*)&WT[(size_t)(n0 + rA1) * 512 + fb + cA1 * 8];
    }
    __syncthreads();

    for (int ch = 0; ch < 24; ch++) {
        int s = ch & 1;
        uint4 pa0, pa1, pb0, pb1;
        if (ch + 1 < 24) {
            int fa = featA(ch + 1), fb = featB(ch + 1);
            pa0 = *(const uint4*)&TP[(size_t)(m0 + rA0) * 512 + fa + cA0 * 8];
            pa1 = *(const uint4*)&TP[(size_t)(m0 + rA1) * 512 + fa + cA1 * 8];
            pb0 = *(const uint4*)&WT[(size_t)(n0 + rA0) * 512 + fb + cA0 * 8];
            pb1 = *(const uint4*)&WT[(size_t)(n0 + rA1) * 512 + fb + cA1 * 8];
        }
#pragma unroll
        for (int ks = 0; ks < 2; ks++) {
            uint32_t afr0[4], afr1[4];
            ldmA(afr0, baseA[s], wr * 32, ks, lane);
            ldmA(afr1, baseA[s], wr * 32 + 16, ks, lane);
#pragma unroll
            for (int nt = 0; nt < 8; nt++) {
                uint32_t bfr[2];
                ldmB(bfr, baseB[s], wc * 64 + nt * 8, ks, lane);
                mma16816(acc[0][nt], afr0, bfr);
                mma16816(acc[1][nt], afr1, bfr);
            }
        }
        if (ch + 1 < 24) {
            int s2 = s ^ 1;
            *(uint4*)((char*)As[s2] + sA0) = pa0;
            *(uint4*)((char*)As[s2] + sA1) = pa1;
            *(uint4*)((char*)Bs[s2] + sA0) = pb0;
            *(uint4*)((char*)Bs[s2] + sA1) = pb1;
        }
        __syncthreads();
    }

    float al = (MODE == 1) ? alpha[li] : 0.0f;
#pragma unroll
    for (int mt = 0; mt < 2; mt++) {
        int r = m0 + wr * 32 + mt * 16 + (lane >> 2);
#pragma unroll
        for (int nt = 0; nt < 8; nt++) {
            int c = n0 + wc * 64 + nt * 8 + (lane & 3) * 2;
            float b0 = bias ? bias[c] : 0.0f, b1 = bias ? bias[c + 1] : 0.0f;
            float* a = acc[mt][nt];
            if (MODE == 0) {
                *(float2*)&C[(size_t)r * Nn + c] = make_float2(a[0] + b0, a[1] + b1);
                *(float2*)&C[(size_t)(r + 8) * Nn + c] = make_float2(a[2] + b0, a[3] + b1);
            } else {
                float2 c0 = *(float2*)&C[(size_t)r * Nn + c];
                float2 c1 = *(float2*)&C[(size_t)(r + 8) * Nn + c];
                c0.x += al * (a[0] + b0); c0.y += al * (a[1] + b1);
                c1.x += al * (a[2] + b0); c1.y += al * (a[3] + b1);
                *(float2*)&C[(size_t)r * Nn + c] = c0;
                *(float2*)&C[(size_t)(r + 8) * Nn + c] = c1;
            }
        }
    }
}

// HMMA distance kernel: 128(n) x 128(m) per CTA, split-bf16 compensated (K=768).
__global__ void __launch_bounds__(256)
k_dist_mma(const __nv_bfloat16* __restrict__ TP, const float* __restrict__ SQ,
           float* __restrict__ D) {
    __shared__ __nv_bfloat16 As[2][128 * 32];
    __shared__ __nv_bfloat16 Bs[2][128 * 32];
    int b = blockIdx.z;
    int n0 = blockIdx.y * 128, m0 = blockIdx.x * 128;
    const __nv_bfloat16* tp = TP + (size_t)b * PN * 512;
    const float* sqb = SQ + b * PN;
    float* Db = D + (size_t)b * PN * PN;
    int tid = threadIdx.x, lane = tid & 31, warp = tid >> 5;
    int wr = warp & 3, wc = warp >> 2;

    uint32_t baseA[2] = { smem_u32(As[0]), smem_u32(As[1]) };
    uint32_t baseB[2] = { smem_u32(Bs[0]), smem_u32(Bs[1]) };

    float acc[2][8][4];
#pragma unroll
    for (int i = 0; i < 2; i++)
#pragma unroll
        for (int j = 0; j < 8; j++)
#pragma unroll
            for (int q = 0; q < 4; q++) acc[i][j][q] = 0.0f;

    int i0 = tid, i1 = tid + 256;
    int rA0 = i0 >> 2, cA0 = i0 & 3, rA1 = i1 >> 2, cA1 = i1 & 3;
    uint32_t sA0 = (uint32_t)rA0 * 64 + (uint32_t)((cA0 ^ ((rA0 >> 1) & 3)) * 16);
    uint32_t sA1 = (uint32_t)rA1 * 64 + (uint32_t)((cA1 ^ ((rA1 >> 1) & 3)) * 16);

    {
        int fa = featA(0), fb = featB(0);
        *(uint4*)((char*)As[0] + sA0) = *(const uint4*)&tp[(size_t)(n0 + rA0) * 512 + fa + cA0 * 8];
        *(uint4*)((char*)As[0] + sA1) = *(const uint4*)&tp[(size_t)(n0 + rA1) * 512 + fa + cA1 * 8];
        *(uint4*)((char*)Bs[0] + sA0) = *(const uint4*)&tp[(size_t)(m0 + rA0) * 512 + fb + cA0 * 8];
        *(uint4*)((char*)Bs[0] + sA1) = *(const uint4*)&tp[(size_t)(m0 + rA1) * 512 + fb + cA1 * 8];
    }
    __syncthreads();

    for (int ch = 0; ch < 24; ch++) {
        int s = ch & 1;
        uint4 pa0, pa1, pb0, pb1;
        if (ch + 1 < 24) {
            int fa = featA(ch + 1), fb = featB(ch + 1);
            pa0 = *(const uint4*)&tp[(size_t)(n0 + rA0) * 512 + fa + cA0 * 8];
            pa1 = *(const uint4*)&tp[(size_t)(n0 + rA1) * 512 + fa + cA1 * 8];
            pb0 = *(const uint4*)&tp[(size_t)(m0 + rA0) * 512 + fb + cA0 * 8];
            pb1 = *(const uint4*)&tp[(size_t)(m0 + rA1) * 512 + fb + cA1 * 8];
        }
#pragma unroll
        for (int ks = 0; ks < 2; ks++) {
            uint32_t afr0[4], afr1[4];
            ldmA(afr0, baseA[s], wr * 32, ks, lane);
            ldmA(afr1, baseA[s], wr * 32 + 16, ks, lane);
#pragma unroll
            for (int nt = 0; nt < 8; nt++) {
                uint32_t bfr[2];
                ldmB(bfr, baseB[s], wc * 64 + nt * 8, ks, lane);
                mma16816(acc[0][nt], afr0, bfr);
                mma16816(acc[1][nt], afr1, bfr);
            }
        }
        if (ch + 1 < 24) {
            int s2 = s ^ 1;
            *(uint4*)((char*)As[s2] + sA0) = pa0;
            *(uint4*)((char*)As[s2] + sA1) = pa1;
            *(uint4*)((char*)Bs[s2] + sA0) = pb0;
            *(uint4*)((char*)Bs[s2] + sA1) = pb1;
        }
        __syncthreads();
    }

#pragma unroll
    for (int mt = 0; mt < 2; mt++) {
        int r = n0 + wr * 32 + mt * 16 + (lane >> 2);
        float sn0 = sqb[r], sn1 = sqb[r + 8];
#pragma unroll
        for (int nt = 0; nt < 8; nt++) {
            int c = m0 + wc * 64 + nt * 8 + (lane & 3) * 2;
            float sm0 = sqb[c], sm1 = sqb[c + 1];
            float* a = acc[mt][nt];
            *(float2*)&Db[(size_t)r * PN + c] =
                make_float2(sn0 + sm0 - 2.0f * a[0], sn0 + sm1 - 2.0f * a[1]);
            *(float2*)&Db[(size_t)(r + 8) * PN + c] =
                make_float2(sn1 + sm0 - 2.0f * a[2], sn1 + sm1 - 2.0f * a[3]);
        }
    }
}

// topk: one warp per row
__global__ void __launch_bounds__(128)
k_topk(const float* __restrict__ D, int* __restrict__ IDX) {
    __shared__ float sd[4][PN];
    int warp = threadIdx.x >> 5, lane = threadIdx.x & 31;
    int p = blockIdx.x * 4 + warp;
    const float* row = D + (size_t)p * PN;
    float* s = sd[warp];
    for (int i = lane; i < PN / 4; i += 32)
        ((float4*)s)[i] = ((const float4*)row)[i];
    __syncwarp();
    float bv = FLT_MAX; int bi = PN;
#pragma unroll 8
    for (int j = 0; j < PN / 32; j++) {
        int idx = lane + 32 * j;
        float v = s[idx];
        if (v < bv) { bv = v; bi = idx; }
    }
    for (int k = 0; k < PK; k++) {
        float v = bv; int i = bi;
#pragma unroll
        for (int o = 16; o > 0; o >>= 1) {
            float v2 = __shfl_xor_sync(0xffffffffu, v, o);
            int i2 = __shfl_xor_sync(0xffffffffu, i, o);
            if (v2 < v || (v2 == v && i2 < i)) { v = v2; i = i2; }
        }
        if (lane == 0) IDX[p * PK + k] = i;
        if ((i & 31) == lane) {
            s[i] = FLT_MAX;
            bv = FLT_MAX; bi = PN;
#pragma unroll 8
            for (int j = 0; j < PN / 32; j++) {
                int idx = lane + 32 * j;
                float w = s[idx];
                if (w < bv) { bv = w; bi = idx; }
            }
        }
        __syncwarp();
    }
}

__global__ void k_gathermax(const float* __restrict__ U, const float* __restrict__ V,
                            const int* __restrict__ IDX, float* __restrict__ OUT) {
    __shared__ int sidx[PK];
    int p = blockIdx.x, h = threadIdx.x;
    int b = p >> 11;
    if (h < PK) sidx[h] = IDX[p * PK + h];
    __syncthreads();
    float m = -FLT_MAX;
    int base = b * PN;
#pragma unroll
    for (int k = 0; k < PK; k++)
        m = fmaxf(m, V[(size_t)(base + sidx[k]) * PH + h]);
    OUT[(size_t)p * PH + h] = U[(size_t)p * PH + h] + m;
}

__global__ void k_bnpart(const float* __restrict__ X, float* __restrict__ psum, float* __restrict__ psq) {
    int blk = blockIdx.x, c = threadIdx.x;
    float s = 0.f, s2 = 0.f;
    int r0 = blk * 128;
    for (int r = 0; r < 128; r++) {
        float v = X[(size_t)(r0 + r) * PH + c];
        s += v; s2 += v * v;
    }
    psum[blk * PH + c] = s;
    psq [blk * PH + c] = s2;
}
// warp-per-channel final reduce: grid 32 x 256 threads (8 warps)
__global__ void k_bnfin(const float* __restrict__ psum, const float* __restrict__ psq,
                        float* __restrict__ mean, float* __restrict__ rstd) {
    int warp = threadIdx.x >> 5, lane = threadIdx.x & 31;
    int c = blockIdx.x * 8 + warp;
    float s = 0.f, s2 = 0.f;
#pragma unroll
    for (int b = lane; b < 128; b += 32) { s += psum[b * PH + c]; s2 += psq[b * PH + c]; }
#pragma unroll
    for (int o = 16; o > 0; o >>= 1) {
        s  += __shfl_down_sync(0xffffffffu, s, o);
        s2 += __shfl_down_sync(0xffffffffu, s2, o);
    }
    if (lane == 0) {
        float m = s * (1.0f / NPTS);
        float var = s2 * (1.0f / NPTS) - m * m;
        mean[c] = m;
        rstd[c] = rsqrtf(var + EPS);
    }
}
template<int WRITE_SQ>
__global__ void k_bnapply(const float* __restrict__ X, float* __restrict__ Y,
                          const float* __restrict__ mean, const float* __restrict__ rstd,
                          const float* __restrict__ g, const float* __restrict__ bt,
                          float* __restrict__ SQ) {
    __shared__ float red[8];
    int c = threadIdx.x;
    size_t i = (size_t)blockIdx.x * PH + c;
    float v = (X[i] - mean[c]) * rstd[c] * g[c] + bt[c];
    v = fmaxf(v, 0.0f);
    Y[i] = v;
    if (WRITE_SQ) {
        float s = v * v;
#pragma unroll
        for (int o = 16; o > 0; o >>= 1) s += __shfl_down_sync(0xffffffffu, s, o);
        if ((c & 31) == 0) red[c >> 5] = s;
        __syncthreads();
        if (c == 0) {
            float t = 0.f;
#pragma unroll
            for (int w = 0; w < 8; w++) t += red[w];
            SQ[blockIdx.x] = t;
        }
    }
}

__global__ void k_pool1(const float* __restrict__ BIG, float* __restrict__ PM) {
    int b = blockIdx.x, chunk = blockIdx.y, g = threadIdx.x;
    float m = -FLT_MAX;
    int n0 = chunk * 128;
    for (int n = 0; n < 128; n++)
        m = fmaxf(m, BIG[(size_t)(b * PN + n0 + n) * PG + g]);
    PM[(b * 16 + chunk) * PG + g] = m;
}
__global__ void k_pool2(const float* __restrict__ PM, float* __restrict__ P) {
    int b = blockIdx.x, g = threadIdx.x;
    float m = -FLT_MAX;
    for (int c = 0; c < 16; c++) m = fmaxf(m, PM[(b * 16 + c) * PG + g]);
    P[b * PG + g] = m;
}

__global__ void k_mlp(const float* __restrict__ P,
                      const float* __restrict__ Wm1, const float* __restrict__ bm1,
                      const float* __restrict__ Wm2, const float* __restrict__ bm2,
                      const float* __restrict__ Wm3, const float* __restrict__ bm3,
                      float* __restrict__ OUT) {
    __shared__ float sp[PG], s1[PM0], s2[PM1];
    int b = blockIdx.x, tid = threadIdx.x;
    for (int j = tid; j < PG; j += 256) sp[j] = P[b * PG + j];
    __syncthreads();
    {
        float acc = bm1[tid];
        for (int k = 0; k < PG; k++) acc += sp[k] * Wm1[k * PM0 + tid];
        s1[tid] = fmaxf(acc, 0.0f);
    }
    __syncthreads();
    if (tid < PM1) {
        float acc = bm2[tid];
        for (int k = 0; k < PM0; k++) acc += s1[k] * Wm2[k * PM1 + tid];
        s2[tid] = fmaxf(acc, 0.0f);
    }
    __syncthreads();
    if (tid < PC) {
        float acc = bm3[tid];
        for (int k = 0; k < PM1; k++) acc += s2[k] * Wm3[k * PC + tid];
        OUT[b * PC + tid] = acc;
    }
}

// ---------------- host orchestration ----------------
extern "C" void kernel_launch(void* const* d_in, const int* in_sizes, int n_in,
                              void* d_out, int out_size) {
    const float* x    = (const float*)d_in[0];
    const float* Wf   = (const float*)d_in[2];
    const float* bf   = (const float*)d_in[3];
    const float* Wnn  = (const float*)d_in[4];
    const float* bnn  = (const float*)d_in[5];
    const float* g1   = (const float*)d_in[6];
    const float* b1   = (const float*)d_in[7];
    const float* We   = (const float*)d_in[8];
    const float* be   = (const float*)d_in[9];
    const float* g2   = (const float*)d_in[10];
    const float* b2   = (const float*)d_in[11];
    const float* Wl   = (const float*)d_in[12];
    const float* bl   = (const float*)d_in[13];
    const float* alpha= (const float*)d_in[14];
    const float* gg   = (const float*)d_in[15];
    const float* bgb  = (const float*)d_in[16];
    const float* Wg   = (const float*)d_in[17];
    const float* bg2  = (const float*)d_in[18];
    const float* Wm1  = (const float*)d_in[19];
    const float* bm1  = (const float*)d_in[20];
    const float* Wm2  = (const float*)d_in[21];
    const float* bm2  = (const float*)d_in[22];
    const float* Wm3  = (const float*)d_in[23];
    const float* bm3  = (const float*)d_in[24];

    float *h_, *t_, *u_, *v_, *sq_, *d_, *psum_, *psq_, *mean_, *rstd_, *big_, *pm_, *p_;
    int* idx_;
    __nv_bfloat16 *tp_, *wt1_, *wt2_;
    cudaGetSymbolAddress((void**)&h_,   g_h);
    cudaGetSymbolAddress((void**)&t_,   g_t);
    cudaGetSymbolAddress((void**)&u_,   g_u);
    cudaGetSymbolAddress((void**)&v_,   g_v);
    cudaGetSymbolAddress((void**)&sq_,  g_sq);
    cudaGetSymbolAddress((void**)&d_,   g_d);
    cudaGetSymbolAddress((void**)&idx_, g_idx);
    cudaGetSymbolAddress((void**)&psum_,g_psum);
    cudaGetSymbolAddress((void**)&psq_, g_psq);
    cudaGetSymbolAddress((void**)&mean_,g_mean);
    cudaGetSymbolAddress((void**)&rstd_,g_rstd);
    cudaGetSymbolAddress((void**)&big_, g_big);
    cudaGetSymbolAddress((void**)&pm_,  g_pm);
    cudaGetSymbolAddress((void**)&p_,   g_p);
    cudaGetSymbolAddress((void**)&tp_,  g_tp);
    cudaGetSymbolAddress((void**)&wt1_, g_wt1);
    cudaGetSymbolAddress((void**)&wt2_, g_wt2);

    k_feat<<<NPTS, PH>>>(x, Wf, bf, h_);

    for (int i = 0; i < PL; i++) {
        const float* src;
        if (i == 0) {
            k_split<<<NPTS, 256>>>(h_, tp_);
            k_wtsplit<<<PH, 256>>>(Wnn, nullptr, wt1_, PH);
            k_gemm_mma<0><<<dim3(PH / 128, NPTS / 128), 256>>>(tp_, wt1_, bnn, t_, PH, nullptr, 0);
            src = t_;
        } else {
            src = h_;
        }
        k_bnpart<<<128, 256>>>(src, psum_, psq_);
        k_bnfin<<<32, 256>>>(psum_, psq_, mean_, rstd_);
        k_bnapply<1><<<NPTS, 256>>>(src, t_, mean_, rstd_, g1 + i * PH, b1 + i * PH, sq_);
        // kNN via HMMA (split bf16)
        k_split<<<NPTS, 256>>>(t_, tp_);
        k_dist_mma<<<dim3(PN / 128, PN / 128, PB), 256>>>(tp_, sq_, d_);
        k_topk<<<NPTS / 4, 128>>>(d_, idx_);
        // edge conv split form: u = t@(A-B)+be, v = t@B; out = u + max_k v[idx]
        const float* WeA = We + (size_t)i * 2 * PH * PH;
        const float* WeB = WeA + PH * PH;
        k_wtsplit<<<PH, 256>>>(WeA, WeB, wt1_, PH);
        k_wtsplit<<<PH, 256>>>(WeB, nullptr, wt2_, PH);
        k_gemm_mma<0><<<dim3(PH / 128, NPTS / 128), 256>>>(tp_, wt1_, be + i * PH, u_, PH, nullptr, 0);
        k_gemm_mma<0><<<dim3(PH / 128, NPTS / 128), 256>>>(tp_, wt2_, nullptr, v_, PH, nullptr, 0);
        k_gathermax<<<NPTS, 256>>>(u_, v_, idx_, u_);
        k_bnpart<<<128, 256>>>(u_, psum_, psq_);
        k_bnfin<<<32, 256>>>(psum_, psq_, mean_, rstd_);
        k_bnapply<0><<<NPTS, 256>>>(u_, t_, mean_, rstd_, g2 + i * PH, b2 + i * PH, nullptr);
        // h += alpha[i] * (t @ Wl + bl)
        k_split<<<NPTS, 256>>>(t_, tp_);
        k_wtsplit<<<PH, 256>>>(Wl + (size_t)i * PH * PH, nullptr, wt1_, PH);
        k_gemm_mma<1><<<dim3(PH / 128, NPTS / 128), 256>>>(tp_, wt1_, bl + i * PH, h_, PH, alpha, i);
    }

    // head
    k_bnpart<<<128, 256>>>(h_, psum_, psq_);
    k_bnfin<<<32, 256>>>(psum_, psq_, mean_, rstd_);
    k_bnapply<0><<<NPTS, 256>>>(h_, t_, mean_, rstd_, gg, bgb, nullptr);
    k_split<<<NPTS, 256>>>(t_, tp_);
    k_wtsplit<<<PG, 256>>>(Wg, nullptr, wt1_, PG);
    k_gemm_mma<0><<<dim3(PG / 128, NPTS / 128), 256>>>(tp_, wt1_, bg2, big_, PG, nullptr, 0);
    k_pool1<<<dim3(PB, 16), PG>>>(big_, pm_);
    k_pool2<<<PB, PG>>>(pm_, p_);
    k_mlp<<<PB, 256>>>(p_, Wm1, bm1, Wm2, bm2, Wm3, bm3, (float*)d_out);
}

// round 6
// speedup vs baseline: 3.0185x; 1.1735x over previous
#include <cuda_runtime.h>
#include <cuda_bf16.h>
#include <float.h>
#include <stdint.h>

// ---------------- problem constants ----------------
#define PB   8
#define PN   2048
#define PH   256
#define PL   4
#define PK   16
#define PG   512
#define PM0  256
#define PM1  128
#define PC   128
#define NPTS (PB * PN)           // 16384
#define EPS  1e-5f

// ---------------- device scratch ----------------
__device__ float g_h [NPTS * PH];
__device__ float g_t [NPTS * PH];
__device__ float g_u [NPTS * PH];
__device__ float g_v [NPTS * PH];
__device__ float g_sq[NPTS];
__device__ float g_d [(size_t)PB * PN * PN];   // 134 MB
__device__ int   g_idx[NPTS * PK];
__device__ float g_psum[128 * PH];
__device__ float g_psq [128 * PH];
__device__ float g_mean[PH];
__device__ float g_rstd[PH];
__device__ float g_big[(size_t)NPTS * PG];
__device__ float g_pm [PB * 16 * PG];
__device__ float g_p  [PB * PG];
__device__ __nv_bfloat16 g_tp [(size_t)NPTS * 512];  // activations: [hi(256) | lo(256)] per row
__device__ __nv_bfloat16 g_wt1[512 * 512];           // weight T split
__device__ __nv_bfloat16 g_wt2[512 * 512];

// ---------------- mma.sync helpers ----------------
__device__ __forceinline__ uint32_t smem_u32(const void* p) {
    uint32_t a;
    asm("{ .reg .u64 t; cvta.to.shared.u64 t, %1; cvt.u32.u64 %0, t; }" : "=r"(a) : "l"(p));
    return a;
}
__device__ __forceinline__ void mma16816(float* c, const uint32_t* a, const uint32_t* b) {
    asm volatile("mma.sync.aligned.m16n8k16.row.col.f32.bf16.bf16.f32 "
        "{%0,%1,%2,%3}, {%4,%5,%6,%7}, {%8,%9}, {%0,%1,%2,%3};"
        : "+f"(c[0]), "+f"(c[1]), "+f"(c[2]), "+f"(c[3])
        : "r"(a[0]), "r"(a[1]), "r"(a[2]), "r"(a[3]), "r"(b[0]), "r"(b[1]));
}
__device__ __forceinline__ void ldmA(uint32_t* a, uint32_t base, int rbase, int ks, int lane) {
    int sub = lane >> 3;
    int r = rbase + (sub & 1) * 8 + (lane & 7);
    int kb = ks * 32 + (sub >> 1) * 16;
    int chunk = (kb >> 4) ^ ((r >> 1) & 3);
    uint32_t addr = base + r * 64 + chunk * 16;
    asm volatile("ldmatrix.sync.aligned.m8n8.x4.shared.b16 {%0,%1,%2,%3}, [%4];"
        : "=r"(a[0]), "=r"(a[1]), "=r"(a[2]), "=r"(a[3]) : "r"(addr));
}
// B fragments for two adjacent 8-col groups in one x4:
// regs {0,1} = group nbase, {2,3} = group nbase+8
__device__ __forceinline__ void ldmB4(uint32_t* b4, uint32_t base, int nbase, int ks, int lane) {
    int g = lane >> 3;                       // 0..3
    int r = nbase + ((g >> 1) << 3) + (lane & 7);
    int kb = ks * 32 + (g & 1) * 16;
    int chunk = (kb >> 4) ^ ((r >> 1) & 3);
    uint32_t addr = base + r * 64 + chunk * 16;
    asm volatile("ldmatrix.sync.aligned.m8n8.x4.shared.b16 {%0,%1,%2,%3}, [%4];"
        : "=r"(b4[0]), "=r"(b4[1]), "=r"(b4[2]), "=r"(b4[3]) : "r"(addr));
}
// term schedule: groups of 8 chunks: 0-7 hiA*hiB, 8-15 hiA*loB, 16-23 loA*hiB
__device__ __forceinline__ int featA(int ch) { return ((ch >> 3) == 2 ? 256 : 0) + (ch & 7) * 32; }
__device__ __forceinline__ int featB(int ch) { return ((ch >> 3) == 1 ? 256 : 0) + (ch & 7) * 32; }

// ---------------- kernels ----------------

__global__ void k_feat(const float* __restrict__ X, const float* __restrict__ Wf,
                       const float* __restrict__ bf, float* __restrict__ H) {
    int p = blockIdx.x, c = threadIdx.x;
    float x0 = X[p * 3 + 0], x1 = X[p * 3 + 1], x2 = X[p * 3 + 2];
    H[(size_t)p * PH + c] = x0 * Wf[c] + x1 * Wf[PH + c] + x2 * Wf[2 * PH + c] + bf[c];
}

__global__ void k_split(const float* __restrict__ T, __nv_bfloat16* __restrict__ TP) {
    int p = blockIdx.x, f = threadIdx.x;
    float v = T[(size_t)p * PH + f];
    __nv_bfloat16 hi = __float2bfloat16(v);
    float rem = v - __bfloat162float(hi);
    TP[(size_t)p * 512 + f] = hi;
    TP[(size_t)p * 512 + 256 + f] = __float2bfloat16(rem);
}

__global__ void k_wtsplit(const float* __restrict__ W, const float* __restrict__ Wsub,
                          __nv_bfloat16* __restrict__ WT, int Nn) {
    int n = blockIdx.x, k = threadIdx.x;
    float v = W[(size_t)k * Nn + n];
    if (Wsub) v -= Wsub[(size_t)k * Nn + n];
    __nv_bfloat16 hi = __float2bfloat16(v);
    float rem = v - __bfloat162float(hi);
    WT[(size_t)n * 512 + k] = hi;
    WT[(size_t)n * 512 + 256 + k] = __float2bfloat16(rem);
}

// Generic split-bf16 HMMA GEMM: C[M,Nn] = A@W (+bias), K=256 (24 chunk iters).
template<int MODE>
__global__ void __launch_bounds__(256)
k_gemm_mma(const __nv_bfloat16* __restrict__ TP, const __nv_bfloat16* __restrict__ WT,
           const float* __restrict__ bias, float* __restrict__ C, int Nn,
           const float* __restrict__ alpha, int li) {
    __shared__ __nv_bfloat16 As[2][128 * 32];
    __shared__ __nv_bfloat16 Bs[2][128 * 32];
    int n0 = blockIdx.x * 128, m0 = blockIdx.y * 128;
    int tid = threadIdx.x, lane = tid & 31, warp = tid >> 5;
    int wr = warp & 3, wc = warp >> 2;

    uint32_t baseA[2] = { smem_u32(As[0]), smem_u32(As[1]) };
    uint32_t baseB[2] = { smem_u32(Bs[0]), smem_u32(Bs[1]) };

    float acc[2][8][4];
#pragma unroll
    for (int i = 0; i < 2; i++)
#pragma unroll
        for (int j = 0; j < 8; j++)
#pragma unroll
            for (int q = 0; q < 4; q++) acc[i][j][q] = 0.0f;

    int i0 = tid, i1 = tid + 256;
    int rA0 = i0 >> 2, cA0 = i0 & 3, rA1 = i1 >> 2, cA1 = i1 & 3;
    uint32_t sA0 = (uint32_t)rA0 * 64 + (uint32_t)((cA0 ^ ((rA0 >> 1) & 3)) * 16);
    uint32_t sA1 = (uint32_t)rA1 * 64 + (uint32_t)((cA1 ^ ((rA1 >> 1) & 3)) * 16);

    {
        int fa = featA(0), fb = featB(0);
        *(uint4*)((char*)As[0] + sA0) = *(const uint4*)&TP[(size_t)(m0 + rA0) * 512 + fa + cA0 * 8];
        *(uint4*)((char*)As[0] + sA1) = *(const uint4*)&TP[(size_t)(m0 + rA1) * 512 + fa + cA1 * 8];
        *(uint4*)((char*)Bs[0] + sA0) = *(const uint4*)&WT[(size_t)(n0 + rA0) * 512 + fb + cA0 * 8];
        *(uint4*)((char*)Bs[0] + sA1) = *(const uint4*)&WT[(size_t)(n0 + rA1) * 512 + fb + cA1 * 8];
    }
    __syncthreads();

    for (int ch = 0; ch < 24; ch++) {
        int s = ch & 1;
        uint4 pa0, pa1, pb0, pb1;
        if (ch + 1 < 24) {
            int fa = featA(ch + 1), fb = featB(ch + 1);
            pa0 = *(const uint4*)&TP[(size_t)(m0 + rA0) * 512 + fa + cA0 * 8];
            pa1 = *(const uint4*)&TP[(size_t)(m0 + rA1) * 512 + fa + cA1 * 8];
            pb0 = *(const uint4*)&WT[(size_t)(n0 + rA0) * 512 + fb + cA0 * 8];
            pb1 = *(const uint4*)&WT[(size_t)(n0 + rA1) * 512 + fb + cA1 * 8];
        }
#pragma unroll
        for (int ks = 0; ks < 2; ks++) {
            uint32_t afr0[4], afr1[4];
            ldmA(afr0, baseA[s], wr * 32, ks, lane);
            ldmA(afr1, baseA[s], wr * 32 + 16, ks, lane);
#pragma unroll
            for (int np = 0; np < 4; np++) {
                uint32_t b4[4];
                ldmB4(b4, baseB[s], wc * 64 + np * 16, ks, lane);
                mma16816(acc[0][2 * np + 0], afr0, b4);
                mma16816(acc[0][2 * np + 1], afr0, b4 + 2);
                mma16816(acc[1][2 * np + 0], afr1, b4);
                mma16816(acc[1][2 * np + 1], afr1, b4 + 2);
            }
        }
        if (ch + 1 < 24) {
            int s2 = s ^ 1;
            *(uint4*)((char*)As[s2] + sA0) = pa0;
            *(uint4*)((char*)As[s2] + sA1) = pa1;
            *(uint4*)((char*)Bs[s2] + sA0) = pb0;
            *(uint4*)((char*)Bs[s2] + sA1) = pb1;
        }
        __syncthreads();
    }

    float al = (MODE == 1) ? alpha[li] : 0.0f;
#pragma unroll
    for (int mt = 0; mt < 2; mt++) {
        int r = m0 + wr * 32 + mt * 16 + (lane >> 2);
#pragma unroll
        for (int nt = 0; nt < 8; nt++) {
            int c = n0 + wc * 64 + nt * 8 + (lane & 3) * 2;
            float b0 = bias ? bias[c] : 0.0f, b1 = bias ? bias[c + 1] : 0.0f;
            float* a = acc[mt][nt];
            if (MODE == 0) {
                *(float2*)&C[(size_t)r * Nn + c] = make_float2(a[0] + b0, a[1] + b1);
                *(float2*)&C[(size_t)(r + 8) * Nn + c] = make_float2(a[2] + b0, a[3] + b1);
            } else {
                float2 c0 = *(float2*)&C[(size_t)r * Nn + c];
                float2 c1 = *(float2*)&C[(size_t)(r + 8) * Nn + c];
                c0.x += al * (a[0] + b0); c0.y += al * (a[1] + b1);
                c1.x += al * (a[2] + b0); c1.y += al * (a[3] + b1);
                *(float2*)&C[(size_t)r * Nn + c] = c0;
                *(float2*)&C[(size_t)(r + 8) * Nn + c] = c1;
            }
        }
    }
}

// HMMA distance: 128(n rows) x 128(m cols) per CTA, split-bf16 (K=768),
// upper-triangular blocks only (m-block >= n-block); off-diagonal blocks also
// write the transposed tile via smem staging (aliased onto the tile buffers).
__global__ void __launch_bounds__(256)
k_dist_mma(const __nv_bfloat16* __restrict__ TP, const float* __restrict__ SQ,
           float* __restrict__ D) {
    int mblk = blockIdx.x, nblk = blockIdx.y;
    if (mblk < nblk) return;   // symmetry: only upper triangle of blocks
    __shared__ __align__(16) float shm_f[8448];   // 33792 B; tiles (32768 B) / staging alias
    __nv_bfloat16* tileA[2] = { (__nv_bfloat16*)shm_f,          (__nv_bfloat16*)shm_f + 4096 };
    __nv_bfloat16* tileB[2] = { (__nv_bfloat16*)shm_f + 8192,   (__nv_bfloat16*)shm_f + 12288 };

    int b = blockIdx.z;
    int n0 = nblk * 128, m0 = mblk * 128;
    const __nv_bfloat16* tp = TP + (size_t)b * PN * 512;
    const float* sqb = SQ + b * PN;
    float* Db = D + (size_t)b * PN * PN;
    int tid = threadIdx.x, lane = tid & 31, warp = tid >> 5;
    int wr = warp & 3, wc = warp >> 2;

    uint32_t baseA[2] = { smem_u32(tileA[0]), smem_u32(tileA[1]) };
    uint32_t baseB[2] = { smem_u32(tileB[0]), smem_u32(tileB[1]) };

    float acc[2][8][4];
#pragma unroll
    for (int i = 0; i < 2; i++)
#pragma unroll
        for (int j = 0; j < 8; j++)
#pragma unroll
            for (int q = 0; q < 4; q++) acc[i][j][q] = 0.0f;

    int i0 = tid, i1 = tid + 256;
    int rA0 = i0 >> 2, cA0 = i0 & 3, rA1 = i1 >> 2, cA1 = i1 & 3;
    uint32_t sA0 = (uint32_t)rA0 * 64 + (uint32_t)((cA0 ^ ((rA0 >> 1) & 3)) * 16);
    uint32_t sA1 = (uint32_t)rA1 * 64 + (uint32_t)((cA1 ^ ((rA1 >> 1) & 3)) * 16);

    {
        int fa = featA(0), fb = featB(0);
        *(uint4*)((char*)tileA[0] + sA0) = *(const uint4*)&tp[(size_t)(n0 + rA0) * 512 + fa + cA0 * 8];
        *(uint4*)((char*)tileA[0] + sA1) = *(const uint4*)&tp[(size_t)(n0 + rA1) * 512 + fa + cA1 * 8];
        *(uint4*)((char*)tileB[0] + sA0) = *(const uint4*)&tp[(size_t)(m0 + rA0) * 512 + fb + cA0 * 8];
        *(uint4*)((char*)tileB[0] + sA1) = *(const uint4*)&tp[(size_t)(m0 + rA1) * 512 + fb + cA1 * 8];
    }
    __syncthreads();

    for (int ch = 0; ch < 24; ch++) {
        int s = ch & 1;
        uint4 pa0, pa1, pb0, pb1;
        if (ch + 1 < 24) {
            int fa = featA(ch + 1), fb = featB(ch + 1);
            pa0 = *(const uint4*)&tp[(size_t)(n0 + rA0) * 512 + fa + cA0 * 8];
            pa1 = *(const uint4*)&tp[(size_t)(n0 + rA1) * 512 + fa + cA1 * 8];
            pb0 = *(const uint4*)&tp[(size_t)(m0 + rA0) * 512 + fb + cA0 * 8];
            pb1 = *(const uint4*)&tp[(size_t)(m0 + rA1) * 512 + fb + cA1 * 8];
        }
#pragma unroll
        for (int ks = 0; ks < 2; ks++) {
            uint32_t afr0[4], afr1[4];
            ldmA(afr0, baseA[s], wr * 32, ks, lane);
            ldmA(afr1, baseA[s], wr * 32 + 16, ks, lane);
#pragma unroll
            for (int np = 0; np < 4; np++) {
                uint32_t b4[4];
                ldmB4(b4, baseB[s], wc * 64 + np * 16, ks, lane);
                mma16816(acc[0][2 * np + 0], afr0, b4);
                mma16816(acc[0][2 * np + 1], afr0, b4 + 2);
                mma16816(acc[1][2 * np + 0], afr1, b4);
                mma16816(acc[1][2 * np + 1], afr1, b4 + 2);
            }
        }
        if (ch + 1 < 24) {
            int s2 = s ^ 1;
            *(uint4*)((char*)tileA[s2] + sA0) = pa0;
            *(uint4*)((char*)tileA[s2] + sA1) = pa1;
            *(uint4*)((char*)tileB[s2] + sA0) = pb0;
            *(uint4*)((char*)tileB[s2] + sA1) = pb1;
        }
        __syncthreads();
    }

    // normal write: D[n][m]
#pragma unroll
    for (int mt = 0; mt < 2; mt++) {
        int r = n0 + wr * 32 + mt * 16 + (lane >> 2);
        float sn0 = sqb[r], sn1 = sqb[r + 8];
#pragma unroll
        for (int nt = 0; nt < 8; nt++) {
            int c = m0 + wc * 64 + nt * 8 + (lane & 3) * 2;
            float sm0 = sqb[c], sm1 = sqb[c + 1];
            float* a = acc[mt][nt];
            *(float2*)&Db[(size_t)r * PN + c] =
                make_float2(sn0 + sm0 - 2.0f * a[0], sn0 + sm1 - 2.0f * a[1]);
            *(float2*)&Db[(size_t)(r + 8) * PN + c] =
                make_float2(sn1 + sm0 - 2.0f * a[2], sn1 + sm1 - 2.0f * a[3]);
        }
    }

    // transposed write for off-diagonal blocks: D[m][n], via smem staging.
    if (mblk != nblk) {
        float* stg = shm_f;   // 32 cols x 128 rows, stride 132 (bank-conflict-free)
        for (int h = 0; h < 2; h++) {
            for (int w = 0; w < 2; w++) {
                if (wc == h) {
#pragma unroll
                    for (int mt = 0; mt < 2; mt++) {
                        int rloc = wr * 32 + mt * 16 + (lane >> 2);
                        float sn0 = sqb[n0 + rloc], sn1 = sqb[n0 + rloc + 8];
#pragma unroll
                        for (int nt2 = 0; nt2 < 4; nt2++) {
                            int nt = w * 4 + nt2;
                            int cw = nt2 * 8 + (lane & 3) * 2;          // window-local col
                            int c = m0 + wc * 64 + nt * 8 + (lane & 3) * 2;
                            float sm0 = sqb[c], sm1 = sqb[c + 1];
                            float* a = acc[mt][nt];
                            stg[cw * 132 + rloc]           = sn0 + sm0 - 2.0f * a[0];
                            stg[(cw + 1) * 132 + rloc]     = sn0 + sm1 - 2.0f * a[1];
                            stg[cw * 132 + rloc + 8]       = sn1 + sm0 - 2.0f * a[2];
                            stg[(cw + 1) * 132 + rloc + 8] = sn1 + sm1 - 2.0f * a[3];
                        }
                    }
                }
                __syncthreads();
                int rowbase = m0 + h * 64 + w * 32;
#pragma unroll
                for (int e = 0; e < 4; e++) {
                    int g4 = tid + e * 256;          // 0..1023 float4s
                    int rr = g4 >> 5, c4 = g4 & 31;
                    float4 v = *(float4*)&stg[rr * 132 + c4 * 4];
                    *(float4*)&Db[(size_t)(rowbase + rr) * PN + n0 + c4 * 4] = v;
                }
                __syncthreads();
            }
        }
    }
}

// topk: one warp per row
__global__ void __launch_bounds__(128)
k_topk(const float* __restrict__ D, int* __restrict__ IDX) {
    __shared__ float sd[4][PN];
    int warp = threadIdx.x >> 5, lane = threadIdx.x & 31;
    int p = blockIdx.x * 4 + warp;
    const float* row = D + (size_t)p * PN;
    float* s = sd[warp];
    for (int i = lane; i < PN / 4; i += 32)
        ((float4*)s)[i] = ((const float4*)row)[i];
    __syncwarp();
    float bv = FLT_MAX; int bi = PN;
#pragma unroll 8
    for (int j = 0; j < PN / 32; j++) {
        int idx = lane + 32 * j;
        float v = s[idx];
        if (v < bv) { bv = v; bi = idx; }
    }
    for (int k = 0; k < PK; k++) {
        float v = bv; int i = bi;
#pragma unroll
        for (int o = 16; o > 0; o >>= 1) {
            float v2 = __shfl_xor_sync(0xffffffffu, v, o);
            int i2 = __shfl_xor_sync(0xffffffffu, i, o);
            if (v2 < v || (v2 == v && i2 < i)) { v = v2; i = i2; }
        }
        if (lane == 0) IDX[p * PK + k] = i;
        if ((i & 31) == lane) {
            s[i] = FLT_MAX;
            bv = FLT_MAX; bi = PN;
#pragma unroll 8
            for (int j = 0; j < PN / 32; j++) {
                int idx = lane + 32 * j;
                float w = s[idx];
                if (w < bv) { bv = w; bi = idx; }
            }
        }
        __syncwarp();
    }
}

__global__ void k_gathermax(const float* __restrict__ U, const float* __restrict__ V,
                            const int* __restrict__ IDX, float* __restrict__ OUT) {
    __shared__ int sidx[PK];
    int p = blockIdx.x, h = threadIdx.x;
    int b = p >> 11;
    if (h < PK) sidx[h] = IDX[p * PK + h];
    __syncthreads();
    float m = -FLT_MAX;
    int base = b * PN;
#pragma unroll
    for (int k = 0; k < PK; k++)
        m = fmaxf(m, V[(size_t)(base + sidx[k]) * PH + h]);
    OUT[(size_t)p * PH + h] = U[(size_t)p * PH + h] + m;
}

__global__ void k_bnpart(const float* __restrict__ X, float* __restrict__ psum, float* __restrict__ psq) {
    int blk = blockIdx.x, c = threadIdx.x;
    float s = 0.f, s2 = 0.f;
    int r0 = blk * 128;
    for (int r = 0; r < 128; r++) {
        float v = X[(size_t)(r0 + r) * PH + c];
        s += v; s2 += v * v;
    }
    psum[blk * PH + c] = s;
    psq [blk * PH + c] = s2;
}
__global__ void k_bnfin(const float* __restrict__ psum, const float* __restrict__ psq,
                        float* __restrict__ mean, float* __restrict__ rstd) {
    int warp = threadIdx.x >> 5, lane = threadIdx.x & 31;
    int c = blockIdx.x * 8 + warp;
    float s = 0.f, s2 = 0.f;
#pragma unroll
    for (int b = lane; b < 128; b += 32) { s += psum[b * PH + c]; s2 += psq[b * PH + c]; }
#pragma unroll
    for (int o = 16; o > 0; o >>= 1) {
        s  += __shfl_down_sync(0xffffffffu, s, o);
        s2 += __shfl_down_sync(0xffffffffu, s2, o);
    }
    if (lane == 0) {
        float m = s * (1.0f / NPTS);
        float var = s2 * (1.0f / NPTS) - m * m;
        mean[c] = m;
        rstd[c] = rsqrtf(var + EPS);
    }
}
template<int WRITE_SQ>
__global__ void k_bnapply(const float* __restrict__ X, float* __restrict__ Y,
                          const float* __restrict__ mean, const float* __restrict__ rstd,
                          const float* __restrict__ g, const float* __restrict__ bt,
                          float* __restrict__ SQ) {
    __shared__ float red[8];
    int c = threadIdx.x;
    size_t i = (size_t)blockIdx.x * PH + c;
    float v = (X[i] - mean[c]) * rstd[c] * g[c] + bt[c];
    v = fmaxf(v, 0.0f);
    Y[i] = v;
    if (WRITE_SQ) {
        float s = v * v;
#pragma unroll
        for (int o = 16; o > 0; o >>= 1) s += __shfl_down_sync(0xffffffffu, s, o);
        if ((c & 31) == 0) red[c >> 5] = s;
        __syncthreads();
        if (c == 0) {
            float t = 0.f;
#pragma unroll
            for (int w = 0; w < 8; w++) t += red[w];
            SQ[blockIdx.x] = t;
        }
    }
}

__global__ void k_pool1(const float* __restrict__ BIG, float* __restrict__ PM) {
    int b = blockIdx.x, chunk = blockIdx.y, g = threadIdx.x;
    float m = -FLT_MAX;
    int n0 = chunk * 128;
    for (int n = 0; n < 128; n++)
        m = fmaxf(m, BIG[(size_t)(b * PN + n0 + n) * PG + g]);
    PM[(b * 16 + chunk) * PG + g] = m;
}
__global__ void k_pool2(const float* __restrict__ PM, float* __restrict__ P) {
    int b = blockIdx.x, g = threadIdx.x;
    float m = -FLT_MAX;
    for (int c = 0; c < 16; c++) m = fmaxf(m, PM[(b * 16 + c) * PG + g]);
    P[b * PG + g] = m;
}

__global__ void k_mlp(const float* __restrict__ P,
                      const float* __restrict__ Wm1, const float* __restrict__ bm1,
                      const float* __restrict__ Wm2, const float* __restrict__ bm2,
                      const float* __restrict__ Wm3, const float* __restrict__ bm3,
                      float* __restrict__ OUT) {
    __shared__ float sp[PG], s1[PM0], s2[PM1];
    int b = blockIdx.x, tid = threadIdx.x;
    for (int j = tid; j < PG; j += 256) sp[j] = P[b * PG + j];
    __syncthreads();
    {
        float acc = bm1[tid];
        for (int k = 0; k < PG; k++) acc += sp[k] * Wm1[k * PM0 + tid];
        s1[tid] = fmaxf(acc, 0.0f);
    }
    __syncthreads();
    if (tid < PM1) {
        float acc = bm2[tid];
        for (int k = 0; k < PM0; k++) acc += s1[k] * Wm2[k * PM1 + tid];
        s2[tid] = fmaxf(acc, 0.0f);
    }
    __syncthreads();
    if (tid < PC) {
        float acc = bm3[tid];
        for (int k = 0; k < PM1; k++) acc += s2[k] * Wm3[k * PC + tid];
        OUT[b * PC + tid] = acc;
    }
}

// ---------------- host orchestration ----------------
extern "C" void kernel_launch(void* const* d_in, const int* in_sizes, int n_in,
                              void* d_out, int out_size) {
    const float* x    = (const float*)d_in[0];
    const float* Wf   = (const float*)d_in[2];
    const float* bf   = (const float*)d_in[3];
    const float* Wnn  = (const float*)d_in[4];
    const float* bnn  = (const float*)d_in[5];
    const float* g1   = (const float*)d_in[6];
    const float* b1   = (const float*)d_in[7];
    const float* We   = (const float*)d_in[8];
    const float* be   = (const float*)d_in[9];
    const float* g2   = (const float*)d_in[10];
    const float* b2   = (const float*)d_in[11];
    const float* Wl   = (const float*)d_in[12];
    const float* bl   = (const float*)d_in[13];
    const float* alpha= (const float*)d_in[14];
    const float* gg   = (const float*)d_in[15];
    const float* bgb  = (const float*)d_in[16];
    const float* Wg   = (const float*)d_in[17];
    const float* bg2  = (const float*)d_in[18];
    const float* Wm1  = (const float*)d_in[19];
    const float* bm1  = (const float*)d_in[20];
    const float* Wm2  = (const float*)d_in[21];
    const float* bm2  = (const float*)d_in[22];
    const float* Wm3  = (const float*)d_in[23];
    const float* bm3  = (const float*)d_in[24];

    float *h_, *t_, *u_, *v_, *sq_, *d_, *psum_, *psq_, *mean_, *rstd_, *big_, *pm_, *p_;
    int* idx_;
    __nv_bfloat16 *tp_, *wt1_, *wt2_;
    cudaGetSymbolAddress((void**)&h_,   g_h);
    cudaGetSymbolAddress((void**)&t_,   g_t);
    cudaGetSymbolAddress((void**)&u_,   g_u);
    cudaGetSymbolAddress((void**)&v_,   g_v);
    cudaGetSymbolAddress((void**)&sq_,  g_sq);
    cudaGetSymbolAddress((void**)&d_,   g_d);
    cudaGetSymbolAddress((void**)&idx_, g_idx);
    cudaGetSymbolAddress((void**)&psum_,g_psum);
    cudaGetSymbolAddress((void**)&psq_, g_psq);
    cudaGetSymbolAddress((void**)&mean_,g_mean);
    cudaGetSymbolAddress((void**)&rstd_,g_rstd);
    cudaGetSymbolAddress((void**)&big_, g_big);
    cudaGetSymbolAddress((void**)&pm_,  g_pm);
    cudaGetSymbolAddress((void**)&p_,   g_p);
    cudaGetSymbolAddress((void**)&tp_,  g_tp);
    cudaGetSymbolAddress((void**)&wt1_, g_wt1);
    cudaGetSymbolAddress((void**)&wt2_, g_wt2);

    k_feat<<<NPTS, PH>>>(x, Wf, bf, h_);

    for (int i = 0; i < PL; i++) {
        const float* src;
        if (i == 0) {
            k_split<<<NPTS, 256>>>(h_, tp_);
            k_wtsplit<<<PH, 256>>>(Wnn, nullptr, wt1_, PH);
            k_gemm_mma<0><<<dim3(PH / 128, NPTS / 128), 256>>>(tp_, wt1_, bnn, t_, PH, nullptr, 0);
            src = t_;
        } else {
            src = h_;
        }
        k_bnpart<<<128, 256>>>(src, psum_, psq_);
        k_bnfin<<<32, 256>>>(psum_, psq_, mean_, rstd_);
        k_bnapply<1><<<NPTS, 256>>>(src, t_, mean_, rstd_, g1 + i * PH, b1 + i * PH, sq_);
        // kNN via HMMA (split bf16), symmetric blocks only
        k_split<<<NPTS, 256>>>(t_, tp_);
        k_dist_mma<<<dim3(PN / 128, PN / 128, PB), 256>>>(tp_, sq_, d_);
        k_topk<<<NPTS / 4, 128>>>(d_, idx_);
        // edge conv split form: u = t@(A-B)+be, v = t@B; out = u + max_k v[idx]
        const float* WeA = We + (size_t)i * 2 * PH * PH;
        const float* WeB = WeA + PH * PH;
        k_wtsplit<<<PH, 256>>>(WeA, WeB, wt1_, PH);
        k_wtsplit<<<PH, 256>>>(WeB, nullptr, wt2_, PH);
        k_gemm_mma<0><<<dim3(PH / 128, NPTS / 128), 256>>>(tp_, wt1_, be + i * PH, u_, PH, nullptr, 0);
        k_gemm_mma<0><<<dim3(PH / 128, NPTS / 128), 256>>>(tp_, wt2_, nullptr, v_, PH, nullptr, 0);
        k_gathermax<<<NPTS, 256>>>(u_, v_, idx_, u_);
        k_bnpart<<<128, 256>>>(u_, psum_, psq_);
        k_bnfin<<<32, 256>>>(psum_, psq_, mean_, rstd_);
        k_bnapply<0><<<NPTS, 256>>>(u_, t_, mean_, rstd_, g2 + i * PH, b2 + i * PH, nullptr);
        // h += alpha[i] * (t @ Wl + bl)
        k_split<<<NPTS, 256>>>(t_, tp_);
        k_wtsplit<<<PH, 256>>>(Wl + (size_t)i * PH * PH, nullptr, wt1_, PH);
        k_gemm_mma<1><<<dim3(PH / 128, NPTS / 128), 256>>>(tp_, wt1_, bl + i * PH, h_, PH, alpha, i);
    }

    // head
    k_bnpart<<<128, 256>>>(h_, psum_, psq_);
    k_bnfin<<<32, 256>>>(psum_, psq_, mean_, rstd_);
    k_bnapply<0><<<NPTS, 256>>>(h_, t_, mean_, rstd_, gg, bgb, nullptr);
    k_split<<<NPTS, 256>>>(t_, tp_);
    k_wtsplit<<<PG, 256>>>(Wg, nullptr, wt1_, PG);
    k_gemm_mma<0><<<dim3(PG / 128, NPTS / 128), 256>>>(tp_, wt1_, bg2, big_, PG, nullptr, 0);
    k_pool1<<<dim3(PB, 16), PG>>>(big_, pm_);
    k_pool2<<<PB, PG>>>(pm_, p_);
    k_mlp<<<PB, 256>>>(p_, Wm1, bm1, Wm2, bm2, Wm3, bm3, (float*)d_out);
}